// round 1
// baseline (speedup 1.0000x reference)
#include <cuda_runtime.h>

#define BATCH  4096
#define SEQ    16
#define EMBED  512
#define HIDDEN 1024
#define HEADS  16
#define DHEAD  64

// Scratch (no cudaMalloc allowed) — device globals.
__device__ float g_Q[(size_t)BATCH * HIDDEN];          // 16 MB
__device__ float g_K[(size_t)BATCH * SEQ * HIDDEN];    // 256 MB
__device__ float g_V[(size_t)BATCH * SEQ * HIDDEN];    // 256 MB

// ---------------------------------------------------------------------------
// Gathered GEMM:  C[m, n] = dot(emb[idx[m], :], W[n, :]) + bias[n]
// N = 2048 split as [0,1024)->W0/b0/C0  and [1024,2048)->W1/b1/C1.
// Tiles BM=128, BN=128, BK=16; 256 threads; 8x8 accumulators per thread.
// mode==0: C0=g_K, C1=g_V (context).  mode==1: C0=g_Q, C1=extC1 (target).
// Grid: (16, M/128).
// ---------------------------------------------------------------------------
__global__ __launch_bounds__(256) void gemm_gather_kernel(
    const int* __restrict__ idx, const float* __restrict__ emb,
    const float* __restrict__ W0, const float* __restrict__ b0,
    const float* __restrict__ W1, const float* __restrict__ b1,
    float* __restrict__ extC1, int mode)
{
    const int bx = blockIdx.x;           // 0..15 over N
    const int by = blockIdx.y;           // over M
    const bool isW1 = (bx >= 8);
    const float* __restrict__ W    = isW1 ? W1 : W0;
    const float* __restrict__ bias = isW1 ? b1 : b0;
    float* __restrict__ C;
    if (mode == 0) C = isW1 ? g_V : g_K;
    else           C = isW1 ? extC1 : g_Q;
    const int n_base = (bx - (isW1 ? 8 : 0)) * 128;

    __shared__ float As[16][128];
    __shared__ float Bs[16][128];

    const int tid  = threadIdx.x;
    const int lrow = tid >> 1;           // 0..127
    const int kcol = (tid & 1) * 8;      // 0 or 8

    const int m_row = by * 128 + lrow;
    const float* __restrict__ arow = emb + (size_t)idx[m_row] * EMBED;
    const float* __restrict__ brow = W + (size_t)(n_base + lrow) * EMBED;

    const int m0 = (tid >> 4) * 8;
    const int n0 = (tid & 15) * 8;

    float acc[8][8];
#pragma unroll
    for (int i = 0; i < 8; i++)
#pragma unroll
        for (int j = 0; j < 8; j++) acc[i][j] = 0.0f;

#pragma unroll 1
    for (int kt = 0; kt < EMBED; kt += 16) {
        // stage to registers (overlaps previous tile's compute)
        float4 a0 = *(const float4*)(arow + kt + kcol);
        float4 a1 = *(const float4*)(arow + kt + kcol + 4);
        float4 w0 = *(const float4*)(brow + kt + kcol);
        float4 w1 = *(const float4*)(brow + kt + kcol + 4);
        __syncthreads();   // previous tile fully consumed
        As[kcol + 0][lrow] = a0.x; As[kcol + 1][lrow] = a0.y;
        As[kcol + 2][lrow] = a0.z; As[kcol + 3][lrow] = a0.w;
        As[kcol + 4][lrow] = a1.x; As[kcol + 5][lrow] = a1.y;
        As[kcol + 6][lrow] = a1.z; As[kcol + 7][lrow] = a1.w;
        Bs[kcol + 0][lrow] = w0.x; Bs[kcol + 1][lrow] = w0.y;
        Bs[kcol + 2][lrow] = w0.z; Bs[kcol + 3][lrow] = w0.w;
        Bs[kcol + 4][lrow] = w1.x; Bs[kcol + 5][lrow] = w1.y;
        Bs[kcol + 6][lrow] = w1.z; Bs[kcol + 7][lrow] = w1.w;
        __syncthreads();

#pragma unroll
        for (int kk = 0; kk < 16; kk++) {
            float a[8], bb[8];
            *(float4*)&a[0]  = *(const float4*)&As[kk][m0];
            *(float4*)&a[4]  = *(const float4*)&As[kk][m0 + 4];
            *(float4*)&bb[0] = *(const float4*)&Bs[kk][n0];
            *(float4*)&bb[4] = *(const float4*)&Bs[kk][n0 + 4];
#pragma unroll
            for (int i = 0; i < 8; i++)
#pragma unroll
                for (int j = 0; j < 8; j++)
                    acc[i][j] = fmaf(a[i], bb[j], acc[i][j]);
        }
    }

    float bv[8];
#pragma unroll
    for (int j = 0; j < 8; j++) bv[j] = bias[n_base + n0 + j];

#pragma unroll
    for (int i = 0; i < 8; i++) {
        const int row = by * 128 + m0 + i;
        float* cp = C + (size_t)row * HIDDEN + n_base + n0;
        float4 o0 = make_float4(acc[i][0] + bv[0], acc[i][1] + bv[1],
                                acc[i][2] + bv[2], acc[i][3] + bv[3]);
        float4 o1 = make_float4(acc[i][4] + bv[4], acc[i][5] + bv[5],
                                acc[i][6] + bv[6], acc[i][7] + bv[7]);
        *(float4*)(cp)     = o0;
        *(float4*)(cp + 4) = o1;
    }
}

// ---------------------------------------------------------------------------
// Attention: one CTA (256 thr) per batch element.
// scores[s,h,g] = Q[h,:].K[s,g,:]/8 ; softmax over g ; ctx = sum_{s,g} A*V
// ---------------------------------------------------------------------------
__global__ __launch_bounds__(256) void attn_kernel(float* __restrict__ out_ctx)
{
    const int b   = blockIdx.x;
    const int tid = threadIdx.x;

    __shared__ float Qs[HEADS][DHEAD];       // 4 KB
    __shared__ float Sc[SEQ * HEADS][17];    // padded: [s*16+h][g], 17.4 KB
    __shared__ float Vs[2][SEQ * DHEAD];     // 2 x 4 KB double buffer

    // stage Q
    ((float4*)Qs)[tid] = ((const float4*)(g_Q + (size_t)b * HIDDEN))[tid];
    __syncthreads();

    // ---- scores: thread = (s,g); computes all 16 h ----
    {
        const int s = tid >> 4, g = tid & 15;
        const float4* krow =
            (const float4*)(g_K + ((size_t)b * SEQ + s) * HIDDEN + g * DHEAD);
        float acc[16];
#pragma unroll
        for (int h = 0; h < 16; h++) acc[h] = 0.0f;
#pragma unroll
        for (int d4 = 0; d4 < 16; d4++) {
            float4 kv = krow[d4];
#pragma unroll
            for (int h = 0; h < 16; h++) {
                float4 qv = *(const float4*)&Qs[h][d4 * 4];
                acc[h] += kv.x * qv.x + kv.y * qv.y + kv.z * qv.z + kv.w * qv.w;
            }
        }
#pragma unroll
        for (int h = 0; h < 16; h++) Sc[s * 16 + h][g] = acc[h] * 0.125f;
    }
    __syncthreads();

    // ---- softmax: thread = (s,h) row over 16 g ----
    {
        float v[16];
        float* row = Sc[tid];
        float mx = -1e30f;
#pragma unroll
        for (int g = 0; g < 16; g++) { v[g] = row[g]; mx = fmaxf(mx, v[g]); }
        float sum = 0.0f;
#pragma unroll
        for (int g = 0; g < 16; g++) { v[g] = __expf(v[g] - mx); sum += v[g]; }
        float inv = 1.0f / sum;
#pragma unroll
        for (int g = 0; g < 16; g++) row[g] = v[g] * inv;
    }
    __syncthreads();

    // ---- AV: thread = (h, d-quad) ----
    const int h  = tid >> 4;
    const int dq = tid & 15;
    float4 acc = make_float4(0.f, 0.f, 0.f, 0.f);
#pragma unroll 1
    for (int s = 0; s < SEQ; s++) {
        float* vbuf = Vs[s & 1];
        ((float4*)vbuf)[tid] =
            ((const float4*)(g_V + ((size_t)b * SEQ + s) * HIDDEN))[tid];
        __syncthreads();
        const float* arow = Sc[s * 16 + h];
#pragma unroll
        for (int g = 0; g < 16; g++) {
            float a = arow[g];
            float4 v = ((const float4*)vbuf)[g * 16 + dq];
            acc.x = fmaf(a, v.x, acc.x);
            acc.y = fmaf(a, v.y, acc.y);
            acc.z = fmaf(a, v.z, acc.z);
            acc.w = fmaf(a, v.w, acc.w);
        }
    }
    *(float4*)(out_ctx + (size_t)b * HIDDEN + h * DHEAD + dq * 4) = acc;
}

// ---------------------------------------------------------------------------
extern "C" void kernel_launch(void* const* d_in, const int* in_sizes, int n_in,
                              void* d_out, int out_size)
{
    const int*   t   = (const int*)d_in[0];
    const int*   c   = (const int*)d_in[1];
    const float* emb = (const float*)d_in[2];
    const float* WQ  = (const float*)d_in[3];
    const float* bQ  = (const float*)d_in[4];
    const float* WK  = (const float*)d_in[5];
    const float* bK  = (const float*)d_in[6];
    const float* WV  = (const float*)d_in[7];
    const float* bV  = (const float*)d_in[8];
    float* out = (float*)d_out;

    float* out_target = out;                              // [B, HIDDEN]
    float* out_ctx    = out + (size_t)BATCH * HIDDEN;     // [B, HIDDEN]

    // context projections: K,V over B*S gathered rows (mode 0 -> g_K, g_V)
    {
        dim3 grid(16, (BATCH * SEQ) / 128);
        gemm_gather_kernel<<<grid, 256>>>(c, emb, WK, bK, WV, bV, nullptr, 0);
    }
    // target projections: Q -> g_Q, target_vector -> out (mode 1)
    {
        dim3 grid(16, BATCH / 128);
        gemm_gather_kernel<<<grid, 256>>>(t, emb, WQ, bQ, WV, bV, out_target, 1);
    }
    // attention -> context_vector
    attn_kernel<<<BATCH, 256>>>(out_ctx);
}

// round 3
// speedup vs baseline: 1.8723x; 1.8723x over previous
#include <cuda_runtime.h>
#include <cuda_bf16.h>
#include <cstdint>

#define BATCH  4096
#define SEQ    16
#define EMBED  512
#define HIDDEN 1024
#define HEADS  16
#define DHEAD  64
#define VOCAB  50257

// ---------------- device scratch (no cudaMalloc allowed) ----------------
__device__ float g_Q[(size_t)BATCH * HIDDEN];                    // 16 MB
__device__ float g_K[(size_t)BATCH * SEQ * HIDDEN];              // 256 MB
__device__ float g_V[(size_t)BATCH * SEQ * HIDDEN];              // 256 MB
__device__ __nv_bfloat16 g_emb_hi[(size_t)VOCAB * EMBED];
__device__ __nv_bfloat16 g_emb_lo[(size_t)VOCAB * EMBED];
__device__ __nv_bfloat16 g_W_hi[3u * HIDDEN * EMBED];            // WQ,WK,WV
__device__ __nv_bfloat16 g_W_lo[3u * HIDDEN * EMBED];

// ---------------- helpers ----------------
__device__ __forceinline__ uint32_t smem_u32(const void* p) {
    uint32_t a;
    asm("{ .reg .u64 t; cvta.to.shared.u64 t, %1; cvt.u32.u64 %0, t; }"
        : "=r"(a) : "l"(p));
    return a;
}
__device__ __forceinline__ void cpa16(uint32_t dst, const void* src) {
    asm volatile("cp.async.cg.shared.global [%0], [%1], 16;"
                 :: "r"(dst), "l"(src) : "memory");
}
#define CP_COMMIT() asm volatile("cp.async.commit_group;" ::: "memory")
#define CP_WAIT(n)  asm volatile("cp.async.wait_group %0;" :: "n"(n) : "memory")

__device__ __forceinline__ void ldm4(uint32_t& r0, uint32_t& r1,
                                     uint32_t& r2, uint32_t& r3, uint32_t a) {
    asm volatile("ldmatrix.sync.aligned.m8n8.x4.shared.b16 {%0,%1,%2,%3}, [%4];"
                 : "=r"(r0), "=r"(r1), "=r"(r2), "=r"(r3) : "r"(a));
}
__device__ __forceinline__ void mma16816(float* d,
                                         uint32_t a0, uint32_t a1, uint32_t a2, uint32_t a3,
                                         uint32_t b0, uint32_t b1) {
    asm volatile(
        "mma.sync.aligned.m16n8k16.row.col.f32.bf16.bf16.f32 "
        "{%0,%1,%2,%3}, {%4,%5,%6,%7}, {%8,%9}, {%0,%1,%2,%3};"
        : "+f"(d[0]), "+f"(d[1]), "+f"(d[2]), "+f"(d[3])
        : "r"(a0), "r"(a1), "r"(a2), "r"(a3), "r"(b0), "r"(b1));
}

// ---------------- fp32 -> bf16 hi/lo split ----------------
__global__ __launch_bounds__(256) void split_kernel(const float* __restrict__ src,
                                                    int dst_sel, int n4) {
    int i = blockIdx.x * blockDim.x + threadIdx.x;
    if (i >= n4) return;
    __nv_bfloat16* hi;
    __nv_bfloat16* lo;
    if (dst_sel == 0) { hi = g_emb_hi; lo = g_emb_lo; }
    else { hi = g_W_hi + (size_t)(dst_sel - 1) * HIDDEN * EMBED;
           lo = g_W_lo + (size_t)(dst_sel - 1) * HIDDEN * EMBED; }
    float4 v = ((const float4*)src)[i];
    __nv_bfloat162 h01 = __floats2bfloat162_rn(v.x, v.y);
    __nv_bfloat162 h23 = __floats2bfloat162_rn(v.z, v.w);
    __nv_bfloat162 l01 = __floats2bfloat162_rn(v.x - __low2float(h01), v.y - __high2float(h01));
    __nv_bfloat162 l23 = __floats2bfloat162_rn(v.z - __low2float(h23), v.w - __high2float(h23));
    ((__nv_bfloat162*)hi)[2 * i]     = h01;
    ((__nv_bfloat162*)hi)[2 * i + 1] = h23;
    ((__nv_bfloat162*)lo)[2 * i]     = l01;
    ((__nv_bfloat162*)lo)[2 * i + 1] = l23;
}

// ---------------- mma.sync gathered GEMM ----------------
// CTA tile 128x128, K chunks of 32. 512 threads = 16 warps (4x4), warp tile 32x32.
// Split-bf16 3 products. grid = (16, 544): by<512 -> context, else target.
// nt<8 -> WQ/WK cols (ncol0 = nt*128), nt>=8 -> WV (ncol0 = (nt-8)*128).
#define ROWB   80                       // smem row stride bytes (32 bf16 + 8 pad)
#define TILEB  (128 * ROWB)             // 10240 B per matrix per stage
#define STAGE  (4 * TILEB)              // Ah, Al, Bh, Bl = 40960 B
#define SMEM_DYN (2 * STAGE)            // 81920 B

__global__ __launch_bounds__(512, 1) void gemm_mma_kernel(
    const int* __restrict__ t, const int* __restrict__ c,
    const float* __restrict__ bQ, const float* __restrict__ bK,
    const float* __restrict__ bV, float* __restrict__ out_target)
{
    extern __shared__ char smdyn[];
    __shared__ float bias_s[128];

    const int tid  = threadIdx.x;
    const int lane = tid & 31;
    const int w    = tid >> 5;

    const int  nt   = blockIdx.x;              // 0..15
    const int  by   = blockIdx.y;              // 0..543
    const bool is_t = (by >= 512);
    const int  m0   = (is_t ? by - 512 : by) * 128;
    const int* idx  = is_t ? t : c;
    const int  msel = (nt < 8) ? (is_t ? 0 : 1) : 2;   // WQ / WK / WV
    const float* bias = (nt < 8) ? (is_t ? bQ : bK) : bV;
    float* Cout = is_t ? ((nt < 8) ? g_Q : out_target)
                       : ((nt < 8) ? g_K : g_V);
    const int ncol0 = (nt & 7) * 128;

    const uint32_t smb = smem_u32(smdyn);

    if (tid < 128) bias_s[tid] = bias[ncol0 + tid];

    // --- cp.async assignments: thread -> (row, 16B seg) for each matrix ---
    const int rloc = tid >> 2;                 // 0..127
    const int seg  = tid & 3;                  // 0..3 (16B each, 64B/row/chunk)
    const int arow = idx[m0 + rloc];
    const __nv_bfloat16* pah = g_emb_hi + (size_t)arow * EMBED + seg * 8;
    const __nv_bfloat16* pal = g_emb_lo + (size_t)arow * EMBED + seg * 8;
    const size_t woff = (size_t)msel * HIDDEN * EMBED
                      + (size_t)(ncol0 + rloc) * EMBED + seg * 8;
    const __nv_bfloat16* pbh = g_W_hi + woff;
    const __nv_bfloat16* pbl = g_W_lo + woff;
    const uint32_t dloc = (uint32_t)(rloc * ROWB + seg * 16);

    auto issue = [&](int k, int buf) {
        const uint32_t d0 = smb + (uint32_t)buf * STAGE + dloc;
        const int ke = k * 32;
        cpa16(d0 + 0 * TILEB, pah + ke);
        cpa16(d0 + 1 * TILEB, pal + ke);
        cpa16(d0 + 2 * TILEB, pbh + ke);
        cpa16(d0 + 3 * TILEB, pbl + ke);
        CP_COMMIT();
    };

    // --- ldmatrix base addresses (per warp) ---
    const int w_m = w & 3;                     // 0..3 -> rows w_m*32
    const int w_n = w >> 2;                    // 0..3 -> cols w_n*32
    const int lrow = lane & 15;
    const int lhalf = (lane >> 4) * 16;        // second 8-col half of k16
    // A tiles: mt in {0,1}; B tiles: g in {0,1}
    uint32_t aBase[2], bBase[2];
#pragma unroll
    for (int mt = 0; mt < 2; mt++)
        aBase[mt] = smb + (uint32_t)((w_m * 32 + mt * 16 + lrow) * ROWB + lhalf);
#pragma unroll
    for (int g = 0; g < 2; g++)
        bBase[g] = smb + 2 * TILEB + (uint32_t)((w_n * 32 + g * 16 + lrow) * ROWB + lhalf);

    float acc[2][4][4];                        // [mt][n8 frag][4]
#pragma unroll
    for (int mt = 0; mt < 2; mt++)
#pragma unroll
        for (int f = 0; f < 4; f++)
#pragma unroll
            for (int q = 0; q < 4; q++) acc[mt][f][q] = 0.0f;

    issue(0, 0);

#pragma unroll 1
    for (int k = 0; k < 16; k++) {
        if (k + 1 < 16) { issue(k + 1, (k + 1) & 1); CP_WAIT(1); }
        else            { CP_WAIT(0); }
        __syncthreads();

        const uint32_t boff = (uint32_t)(k & 1) * STAGE;
#pragma unroll
        for (int ks = 0; ks < 2; ks++) {
            const uint32_t off = boff + ks * 32;
            uint32_t ah[2][4], al[2][4], bh[2][4], bl[2][4];
#pragma unroll
            for (int mt = 0; mt < 2; mt++) {
                ldm4(ah[mt][0], ah[mt][1], ah[mt][2], ah[mt][3], aBase[mt] + off);
                ldm4(al[mt][0], al[mt][1], al[mt][2], al[mt][3], aBase[mt] + off + TILEB);
            }
#pragma unroll
            for (int g = 0; g < 2; g++) {
                ldm4(bh[g][0], bh[g][1], bh[g][2], bh[g][3], bBase[g] + off);
                ldm4(bl[g][0], bl[g][1], bl[g][2], bl[g][3], bBase[g] + off + TILEB);
            }
#pragma unroll
            for (int mt = 0; mt < 2; mt++)
#pragma unroll
                for (int g = 0; g < 2; g++)
#pragma unroll
                    for (int j = 0; j < 2; j++) {
                        float* d = acc[mt][g * 2 + j];
                        mma16816(d, ah[mt][0], ah[mt][1], ah[mt][2], ah[mt][3],
                                 bh[g][j], bh[g][j + 2]);
                        mma16816(d, ah[mt][0], ah[mt][1], ah[mt][2], ah[mt][3],
                                 bl[g][j], bl[g][j + 2]);
                        mma16816(d, al[mt][0], al[mt][1], al[mt][2], al[mt][3],
                                 bh[g][j], bh[g][j + 2]);
                    }
        }
        __syncthreads();
    }

    // --- epilogue: d-frag thread mapping: rows (lane>>2, +8), cols (lane&3)*2 ---
#pragma unroll
    for (int mt = 0; mt < 2; mt++) {
        const int r0 = m0 + w_m * 32 + mt * 16 + (lane >> 2);
#pragma unroll
        for (int g = 0; g < 2; g++)
#pragma unroll
            for (int j = 0; j < 2; j++) {
                const int cl = w_n * 32 + g * 16 + j * 8 + (lane & 3) * 2;
                const float* d = acc[mt][g * 2 + j];
                float2 v0 = make_float2(d[0] + bias_s[cl], d[1] + bias_s[cl + 1]);
                float2 v1 = make_float2(d[2] + bias_s[cl], d[3] + bias_s[cl + 1]);
                *(float2*)(Cout + (size_t)r0 * HIDDEN + ncol0 + cl)       = v0;
                *(float2*)(Cout + (size_t)(r0 + 8) * HIDDEN + ncol0 + cl) = v1;
            }
    }
}

// ---------------- attention (unchanged, passing since round 1) ----------------
__global__ __launch_bounds__(256) void attn_kernel(float* __restrict__ out_ctx)
{
    const int b   = blockIdx.x;
    const int tid = threadIdx.x;

    __shared__ float Qs[HEADS][DHEAD];
    __shared__ float Sc[SEQ * HEADS][17];
    __shared__ float Vs[2][SEQ * DHEAD];

    ((float4*)Qs)[tid] = ((const float4*)(g_Q + (size_t)b * HIDDEN))[tid];
    __syncthreads();

    {
        const int s = tid >> 4, g = tid & 15;
        const float4* krow =
            (const float4*)(g_K + ((size_t)b * SEQ + s) * HIDDEN + g * DHEAD);
        float acc[16];
#pragma unroll
        for (int h = 0; h < 16; h++) acc[h] = 0.0f;
#pragma unroll
        for (int d4 = 0; d4 < 16; d4++) {
            float4 kv = krow[d4];
#pragma unroll
            for (int h = 0; h < 16; h++) {
                float4 qv = *(const float4*)&Qs[h][d4 * 4];
                acc[h] += kv.x * qv.x + kv.y * qv.y + kv.z * qv.z + kv.w * qv.w;
            }
        }
#pragma unroll
        for (int h = 0; h < 16; h++) Sc[s * 16 + h][g] = acc[h] * 0.125f;
    }
    __syncthreads();

    {
        float v[16];
        float* row = Sc[tid];
        float mx = -1e30f;
#pragma unroll
        for (int g = 0; g < 16; g++) { v[g] = row[g]; mx = fmaxf(mx, v[g]); }
        float sum = 0.0f;
#pragma unroll
        for (int g = 0; g < 16; g++) { v[g] = __expf(v[g] - mx); sum += v[g]; }
        float inv = 1.0f / sum;
#pragma unroll
        for (int g = 0; g < 16; g++) row[g] = v[g] * inv;
    }
    __syncthreads();

    const int h  = tid >> 4;
    const int dq = tid & 15;
    float4 acc = make_float4(0.f, 0.f, 0.f, 0.f);
#pragma unroll 1
    for (int s = 0; s < SEQ; s++) {
        float* vbuf = Vs[s & 1];
        ((float4*)vbuf)[tid] =
            ((const float4*)(g_V + ((size_t)b * SEQ + s) * HIDDEN))[tid];
        __syncthreads();
        const float* arow = Sc[s * 16 + h];
#pragma unroll
        for (int g = 0; g < 16; g++) {
            float a = arow[g];
            float4 v = ((const float4*)vbuf)[g * 16 + dq];
            acc.x = fmaf(a, v.x, acc.x);
            acc.y = fmaf(a, v.y, acc.y);
            acc.z = fmaf(a, v.z, acc.z);
            acc.w = fmaf(a, v.w, acc.w);
        }
    }
    *(float4*)(out_ctx + (size_t)b * HIDDEN + h * DHEAD + dq * 4) = acc;
}

// ---------------------------------------------------------------------------
extern "C" void kernel_launch(void* const* d_in, const int* in_sizes, int n_in,
                              void* d_out, int out_size)
{
    const int*   t   = (const int*)d_in[0];
    const int*   c   = (const int*)d_in[1];
    const float* emb = (const float*)d_in[2];
    const float* WQ  = (const float*)d_in[3];
    const float* bQ  = (const float*)d_in[4];
    const float* WK  = (const float*)d_in[5];
    const float* bK  = (const float*)d_in[6];
    const float* WV  = (const float*)d_in[7];
    const float* bV  = (const float*)d_in[8];
    float* out = (float*)d_out;

    float* out_target = out;
    float* out_ctx    = out + (size_t)BATCH * HIDDEN;

    // precision split prologue
    {
        int n4e = (VOCAB * EMBED) / 4;
        split_kernel<<<(n4e + 255) / 256, 256>>>(emb, 0, n4e);
        int n4w = (HIDDEN * EMBED) / 4;
        split_kernel<<<(n4w + 255) / 256, 256>>>(WQ, 1, n4w);
        split_kernel<<<(n4w + 255) / 256, 256>>>(WK, 2, n4w);
        split_kernel<<<(n4w + 255) / 256, 256>>>(WV, 3, n4w);
    }

    // tensor-core GEMMs (mma.sync): context (K,V) + target (Q, target_vector)
    cudaFuncSetAttribute(gemm_mma_kernel,
                         cudaFuncAttributeMaxDynamicSharedMemorySize, SMEM_DYN);
    {
        dim3 grid(16, 544);
        gemm_mma_kernel<<<grid, 512, SMEM_DYN>>>(t, c, bQ, bK, bV, out_target);
    }

    // attention -> context_vector
    attn_kernel<<<BATCH, 256>>>(out_ctx);
}

// round 4
// speedup vs baseline: 3.3901x; 1.8106x over previous
#include <cuda_runtime.h>
#include <cuda_fp16.h>
#include <cstdint>

#define BATCH  4096
#define SEQ    16
#define EMBED  512
#define HIDDEN 1024
#define HEADS  16
#define DHEAD  64
#define VOCAB  50257

// ---------------- device scratch (no cudaMalloc allowed) ----------------
__device__ float  g_Q[(size_t)BATCH * HIDDEN];                   // 16 MB (fp32)
__device__ __half g_Kh[(size_t)BATCH * SEQ * HIDDEN];            // 128 MB
__device__ __half g_Vh[(size_t)BATCH * SEQ * HIDDEN];            // 128 MB
__device__ __half g_emb_h[(size_t)VOCAB * EMBED];                // ~49 MB
__device__ __half g_W_h[3u * HIDDEN * EMBED];                    // WQ,WK,WV fp16

// ---------------- helpers ----------------
__device__ __forceinline__ uint32_t smem_u32(const void* p) {
    uint32_t a;
    asm("{ .reg .u64 t; cvta.to.shared.u64 t, %1; cvt.u32.u64 %0, t; }"
        : "=r"(a) : "l"(p));
    return a;
}
__device__ __forceinline__ void cpa16(uint32_t dst, const void* src) {
    asm volatile("cp.async.cg.shared.global [%0], [%1], 16;"
                 :: "r"(dst), "l"(src) : "memory");
}
#define CP_COMMIT() asm volatile("cp.async.commit_group;" ::: "memory")
#define CP_WAIT(n)  asm volatile("cp.async.wait_group %0;" :: "n"(n) : "memory")

__device__ __forceinline__ void ldm4(uint32_t& r0, uint32_t& r1,
                                     uint32_t& r2, uint32_t& r3, uint32_t a) {
    asm volatile("ldmatrix.sync.aligned.m8n8.x4.shared.b16 {%0,%1,%2,%3}, [%4];"
                 : "=r"(r0), "=r"(r1), "=r"(r2), "=r"(r3) : "r"(a));
}
__device__ __forceinline__ void mma16816(float* d,
                                         uint32_t a0, uint32_t a1, uint32_t a2, uint32_t a3,
                                         uint32_t b0, uint32_t b1) {
    asm volatile(
        "mma.sync.aligned.m16n8k16.row.col.f32.f16.f16.f32 "
        "{%0,%1,%2,%3}, {%4,%5,%6,%7}, {%8,%9}, {%0,%1,%2,%3};"
        : "+f"(d[0]), "+f"(d[1]), "+f"(d[2]), "+f"(d[3])
        : "r"(a0), "r"(a1), "r"(a2), "r"(a3), "r"(b0), "r"(b1));
}

// ---------------- fp32 -> fp16 convert ----------------
// dst_sel: 0 = emb, 1 = WQ, 2 = WK, 3 = WV
__global__ __launch_bounds__(256) void conv_kernel(const float* __restrict__ src,
                                                   int dst_sel, int n4) {
    int i = blockIdx.x * blockDim.x + threadIdx.x;
    if (i >= n4) return;
    __half* dst = (dst_sel == 0) ? g_emb_h
                                 : g_W_h + (size_t)(dst_sel - 1) * HIDDEN * EMBED;
    float4 v = ((const float4*)src)[i];
    __half2 h01 = __floats2half2_rn(v.x, v.y);
    __half2 h23 = __floats2half2_rn(v.z, v.w);
    ((__half2*)dst)[2 * i]     = h01;
    ((__half2*)dst)[2 * i + 1] = h23;
}

// ---------------- mma.sync gathered GEMM (single-pass fp16) ----------------
// CTA tile 128x128, K chunks of 32. 512 threads = 16 warps (4x4), warp tile 32x32.
// grid = (16, 544): by<512 -> context rows (idx=c), else target rows (idx=t).
// nt<8 -> WQ/WK cols (ncol0 = nt*128), nt>=8 -> WV (ncol0 = (nt-8)*128).
#define ROWB   80                       // smem row stride bytes (64 B data + 16 pad)
#define TILEB  (128 * ROWB)             // 10240 B per matrix per stage
#define STAGE  (2 * TILEB)              // A, B = 20480 B
#define SMEM_DYN (2 * STAGE)            // 40960 B

__global__ __launch_bounds__(512, 1) void gemm_mma_kernel(
    const int* __restrict__ t, const int* __restrict__ c,
    const float* __restrict__ bQ, const float* __restrict__ bK,
    const float* __restrict__ bV, float* __restrict__ out_target)
{
    extern __shared__ char smdyn[];
    __shared__ float bias_s[128];

    const int tid  = threadIdx.x;
    const int lane = tid & 31;
    const int w    = tid >> 5;

    const int  nt   = blockIdx.x;              // 0..15
    const int  by   = blockIdx.y;              // 0..543
    const bool is_t = (by >= 512);
    const int  m0   = (is_t ? by - 512 : by) * 128;
    const int* idx  = is_t ? t : c;
    const int  msel = (nt < 8) ? (is_t ? 0 : 1) : 2;   // WQ / WK / WV
    const float* bias = (nt < 8) ? (is_t ? bQ : bK) : bV;
    // outputs: context -> fp16 K/V scratch; target -> fp32 Q / out_target
    float*  CoutF = is_t ? ((nt < 8) ? g_Q : out_target) : nullptr;
    __half* CoutH = is_t ? nullptr : ((nt < 8) ? g_Kh : g_Vh);
    const int ncol0 = (nt & 7) * 128;

    const uint32_t smb = smem_u32(smdyn);

    if (tid < 128) bias_s[tid] = bias[ncol0 + tid];

    // --- cp.async: thread -> (row, 16B seg); 64B of fp16 per row per chunk ---
    const int rloc = tid >> 2;                 // 0..127
    const int seg  = tid & 3;                  // 0..3
    const int arow = idx[m0 + rloc];
    const __half* pa = g_emb_h + (size_t)arow * EMBED + seg * 8;
    const __half* pb = g_W_h + (size_t)msel * HIDDEN * EMBED
                     + (size_t)(ncol0 + rloc) * EMBED + seg * 8;
    const uint32_t dloc = (uint32_t)(rloc * ROWB + seg * 16);

    auto issue = [&](int k, int buf) {
        const uint32_t d0 = smb + (uint32_t)buf * STAGE + dloc;
        const int ke = k * 32;
        cpa16(d0 + 0 * TILEB, pa + ke);
        cpa16(d0 + 1 * TILEB, pb + ke);
        CP_COMMIT();
    };

    // --- ldmatrix base addresses (per warp) ---
    const int w_m = w & 3;
    const int w_n = w >> 2;
    const int lrow = lane & 15;
    const int lhalf = (lane >> 4) * 16;
    uint32_t aBase[2], bBase[2];
#pragma unroll
    for (int mt = 0; mt < 2; mt++)
        aBase[mt] = smb + (uint32_t)((w_m * 32 + mt * 16 + lrow) * ROWB + lhalf);
#pragma unroll
    for (int g = 0; g < 2; g++)
        bBase[g] = smb + TILEB + (uint32_t)((w_n * 32 + g * 16 + lrow) * ROWB + lhalf);

    float acc[2][4][4];
#pragma unroll
    for (int mt = 0; mt < 2; mt++)
#pragma unroll
        for (int f = 0; f < 4; f++)
#pragma unroll
            for (int q = 0; q < 4; q++) acc[mt][f][q] = 0.0f;

    issue(0, 0);

#pragma unroll 1
    for (int k = 0; k < 16; k++) {
        if (k + 1 < 16) { issue(k + 1, (k + 1) & 1); CP_WAIT(1); }
        else            { CP_WAIT(0); }
        __syncthreads();

        const uint32_t boff = (uint32_t)(k & 1) * STAGE;
#pragma unroll
        for (int ks = 0; ks < 2; ks++) {
            const uint32_t off = boff + ks * 32;
            uint32_t a[2][4], b[2][4];
#pragma unroll
            for (int mt = 0; mt < 2; mt++)
                ldm4(a[mt][0], a[mt][1], a[mt][2], a[mt][3], aBase[mt] + off);
#pragma unroll
            for (int g = 0; g < 2; g++)
                ldm4(b[g][0], b[g][1], b[g][2], b[g][3], bBase[g] + off);
#pragma unroll
            for (int mt = 0; mt < 2; mt++)
#pragma unroll
                for (int g = 0; g < 2; g++)
#pragma unroll
                    for (int j = 0; j < 2; j++)
                        mma16816(acc[mt][g * 2 + j],
                                 a[mt][0], a[mt][1], a[mt][2], a[mt][3],
                                 b[g][j], b[g][j + 2]);
        }
        __syncthreads();
    }

    // --- epilogue ---
#pragma unroll
    for (int mt = 0; mt < 2; mt++) {
        const int r0 = m0 + w_m * 32 + mt * 16 + (lane >> 2);
#pragma unroll
        for (int g = 0; g < 2; g++)
#pragma unroll
            for (int j = 0; j < 2; j++) {
                const int cl = w_n * 32 + g * 16 + j * 8 + (lane & 3) * 2;
                const float* d = acc[mt][g * 2 + j];
                const float b0 = bias_s[cl], b1 = bias_s[cl + 1];
                if (CoutH) {
                    __half2 v0 = __floats2half2_rn(d[0] + b0, d[1] + b1);
                    __half2 v1 = __floats2half2_rn(d[2] + b0, d[3] + b1);
                    *(__half2*)(CoutH + (size_t)r0 * HIDDEN + ncol0 + cl)       = v0;
                    *(__half2*)(CoutH + (size_t)(r0 + 8) * HIDDEN + ncol0 + cl) = v1;
                } else {
                    float2 v0 = make_float2(d[0] + b0, d[1] + b1);
                    float2 v1 = make_float2(d[2] + b0, d[3] + b1);
                    *(float2*)(CoutF + (size_t)r0 * HIDDEN + ncol0 + cl)       = v0;
                    *(float2*)(CoutF + (size_t)(r0 + 8) * HIDDEN + ncol0 + cl) = v1;
                }
            }
    }
}

// ---------------- attention (fp16 K/V, fp32 Q) ----------------
__global__ __launch_bounds__(256) void attn_kernel(float* __restrict__ out_ctx)
{
    const int b   = blockIdx.x;
    const int tid = threadIdx.x;

    __shared__ float Qs[HEADS][DHEAD];
    __shared__ float Sc[SEQ * HEADS][17];
    __shared__ float Vs[2][SEQ * DHEAD];

    ((float4*)Qs)[tid] = ((const float4*)(g_Q + (size_t)b * HIDDEN))[tid];
    __syncthreads();

    // ---- scores: thread = (s,g) computes all 16 h ----
    {
        const int s = tid >> 4, g = tid & 15;
        const uint2* krow =
            (const uint2*)(g_Kh + ((size_t)b * SEQ + s) * HIDDEN + g * DHEAD);
        float acc[16];
#pragma unroll
        for (int h = 0; h < 16; h++) acc[h] = 0.0f;
#pragma unroll
        for (int d4 = 0; d4 < 16; d4++) {
            uint2 raw = krow[d4];
            float2 f0 = __half22float2(*(__half2*)&raw.x);
            float2 f1 = __half22float2(*(__half2*)&raw.y);
#pragma unroll
            for (int h = 0; h < 16; h++) {
                float4 qv = *(const float4*)&Qs[h][d4 * 4];
                acc[h] += f0.x * qv.x + f0.y * qv.y + f1.x * qv.z + f1.y * qv.w;
            }
        }
#pragma unroll
        for (int h = 0; h < 16; h++) Sc[s * 16 + h][g] = acc[h] * 0.125f;
    }
    __syncthreads();

    // ---- softmax over g ----
    {
        float v[16];
        float* row = Sc[tid];
        float mx = -1e30f;
#pragma unroll
        for (int g = 0; g < 16; g++) { v[g] = row[g]; mx = fmaxf(mx, v[g]); }
        float sum = 0.0f;
#pragma unroll
        for (int g = 0; g < 16; g++) { v[g] = __expf(v[g] - mx); sum += v[g]; }
        float inv = 1.0f / sum;
#pragma unroll
        for (int g = 0; g < 16; g++) row[g] = v[g] * inv;
    }
    __syncthreads();

    // ---- AV: thread = (h, d-quad) ----
    const int h  = tid >> 4;
    const int dq = tid & 15;
    float4 acc = make_float4(0.f, 0.f, 0.f, 0.f);
#pragma unroll 1
    for (int s = 0; s < SEQ; s++) {
        float* vbuf = Vs[s & 1];
        {
            uint2 raw = ((const uint2*)(g_Vh + ((size_t)b * SEQ + s) * HIDDEN))[tid];
            float2 f0 = __half22float2(*(__half2*)&raw.x);
            float2 f1 = __half22float2(*(__half2*)&raw.y);
            ((float4*)vbuf)[tid] = make_float4(f0.x, f0.y, f1.x, f1.y);
        }
        __syncthreads();
        const float* arow = Sc[s * 16 + h];
#pragma unroll
        for (int g = 0; g < 16; g++) {
            float a = arow[g];
            float4 v = ((const float4*)vbuf)[g * 16 + dq];
            acc.x = fmaf(a, v.x, acc.x);
            acc.y = fmaf(a, v.y, acc.y);
            acc.z = fmaf(a, v.z, acc.z);
            acc.w = fmaf(a, v.w, acc.w);
        }
    }
    *(float4*)(out_ctx + (size_t)b * HIDDEN + h * DHEAD + dq * 4) = acc;
}

// ---------------------------------------------------------------------------
extern "C" void kernel_launch(void* const* d_in, const int* in_sizes, int n_in,
                              void* d_out, int out_size)
{
    const int*   t   = (const int*)d_in[0];
    const int*   c   = (const int*)d_in[1];
    const float* emb = (const float*)d_in[2];
    const float* WQ  = (const float*)d_in[3];
    const float* bQ  = (const float*)d_in[4];
    const float* WK  = (const float*)d_in[5];
    const float* bK  = (const float*)d_in[6];
    const float* WV  = (const float*)d_in[7];
    const float* bV  = (const float*)d_in[8];
    float* out = (float*)d_out;

    float* out_target = out;
    float* out_ctx    = out + (size_t)BATCH * HIDDEN;

    // fp32 -> fp16 converts
    {
        int n4e = (VOCAB * EMBED) / 4;
        conv_kernel<<<(n4e + 255) / 256, 256>>>(emb, 0, n4e);
        int n4w = (HIDDEN * EMBED) / 4;
        conv_kernel<<<(n4w + 255) / 256, 256>>>(WQ, 1, n4w);
        conv_kernel<<<(n4w + 255) / 256, 256>>>(WK, 2, n4w);
        conv_kernel<<<(n4w + 255) / 256, 256>>>(WV, 3, n4w);
    }

    // tensor-core GEMMs (single-pass fp16 mma.sync)
    cudaFuncSetAttribute(gemm_mma_kernel,
                         cudaFuncAttributeMaxDynamicSharedMemorySize, SMEM_DYN);
    {
        dim3 grid(16, 544);
        gemm_mma_kernel<<<grid, 512, SMEM_DYN>>>(t, c, bQ, bK, bV, out_target);
    }

    // attention -> context_vector
    attn_kernel<<<BATCH, 256>>>(out_ctx);
}

// round 5
// speedup vs baseline: 3.5659x; 1.0519x over previous
#include <cuda_runtime.h>
#include <cuda_fp16.h>
#include <cstdint>

#define BATCH  4096
#define SEQ    16
#define EMBED  512
#define HIDDEN 1024
#define HEADS  16
#define DHEAD  64
#define VOCAB  50257

// ---------------- device scratch (no cudaMalloc allowed) ----------------
__device__ float  g_Q[(size_t)BATCH * HIDDEN];                   // 16 MB (fp32)
__device__ __half g_Kh[(size_t)BATCH * SEQ * HIDDEN];            // 128 MB
__device__ __half g_Vh[(size_t)BATCH * SEQ * HIDDEN];            // 128 MB
__device__ __half g_emb_h[(size_t)VOCAB * EMBED];                // ~49 MB
__device__ __half g_W_h[3u * HIDDEN * EMBED];                    // WQ,WK,WV fp16

// ---------------- helpers ----------------
__device__ __forceinline__ uint32_t smem_u32(const void* p) {
    uint32_t a;
    asm("{ .reg .u64 t; cvta.to.shared.u64 t, %1; cvt.u32.u64 %0, t; }"
        : "=r"(a) : "l"(p));
    return a;
}
__device__ __forceinline__ void cpa16(uint32_t dst, const void* src) {
    asm volatile("cp.async.cg.shared.global [%0], [%1], 16;"
                 :: "r"(dst), "l"(src) : "memory");
}
#define CP_COMMIT() asm volatile("cp.async.commit_group;" ::: "memory")
#define CP_WAIT(n)  asm volatile("cp.async.wait_group %0;" :: "n"(n) : "memory")

__device__ __forceinline__ void ldm4(uint32_t& r0, uint32_t& r1,
                                     uint32_t& r2, uint32_t& r3, uint32_t a) {
    asm volatile("ldmatrix.sync.aligned.m8n8.x4.shared.b16 {%0,%1,%2,%3}, [%4];"
                 : "=r"(r0), "=r"(r1), "=r"(r2), "=r"(r3) : "r"(a));
}
__device__ __forceinline__ void mma16816(float* d,
                                         uint32_t a0, uint32_t a1, uint32_t a2, uint32_t a3,
                                         uint32_t b0, uint32_t b1) {
    asm volatile(
        "mma.sync.aligned.m16n8k16.row.col.f32.f16.f16.f32 "
        "{%0,%1,%2,%3}, {%4,%5,%6,%7}, {%8,%9}, {%0,%1,%2,%3};"
        : "+f"(d[0]), "+f"(d[1]), "+f"(d[2]), "+f"(d[3])
        : "r"(a0), "r"(a1), "r"(a2), "r"(a3), "r"(b0), "r"(b1));
}

// ---------------- fp32 -> fp16 convert ----------------
__global__ __launch_bounds__(256) void conv_kernel(const float* __restrict__ src,
                                                   int dst_sel, int n4) {
    int i = blockIdx.x * blockDim.x + threadIdx.x;
    if (i >= n4) return;
    __half* dst = (dst_sel == 0) ? g_emb_h
                                 : g_W_h + (size_t)(dst_sel - 1) * HIDDEN * EMBED;
    float4 v = ((const float4*)src)[i];
    ((__half2*)dst)[2 * i]     = __floats2half2_rn(v.x, v.y);
    ((__half2*)dst)[2 * i + 1] = __floats2half2_rn(v.z, v.w);
}

// ---------------- mma.sync gathered GEMM (fp16, 4-stage pipeline) ----------------
// CTA tile 128x128, K chunks of 32, 4 cp.async stages, 1 barrier per chunk.
// 512 threads = 16 warps (4x4), warp tile 32x32.
// grid = (16, 544): by<512 -> context rows (idx=c), else target rows (idx=t).
#define ROWB    80                      // smem row stride bytes (64 B data + 16 pad)
#define TILEB   (128 * ROWB)            // 10240 B per matrix per stage
#define STAGEB  (2 * TILEB)             // A + B = 20480 B
#define NSTAGE  4
#define SMEM_DYN (NSTAGE * STAGEB)      // 81920 B

__global__ __launch_bounds__(512, 1) void gemm_mma_kernel(
    const int* __restrict__ t, const int* __restrict__ c,
    const float* __restrict__ bQ, const float* __restrict__ bK,
    const float* __restrict__ bV, float* __restrict__ out_target)
{
    extern __shared__ char smdyn[];
    __shared__ float bias_s[128];

    const int tid  = threadIdx.x;
    const int lane = tid & 31;
    const int w    = tid >> 5;

    const int  nt   = blockIdx.x;              // 0..15
    const int  by   = blockIdx.y;              // 0..543
    const bool is_t = (by >= 512);
    const int  m0   = (is_t ? by - 512 : by) * 128;
    const int* idx  = is_t ? t : c;
    const int  msel = (nt < 8) ? (is_t ? 0 : 1) : 2;   // WQ / WK / WV
    const float* bias = (nt < 8) ? (is_t ? bQ : bK) : bV;
    float*  CoutF = is_t ? ((nt < 8) ? g_Q : out_target) : nullptr;
    __half* CoutH = is_t ? nullptr : ((nt < 8) ? g_Kh : g_Vh);
    const int ncol0 = (nt & 7) * 128;

    const uint32_t smb = smem_u32(smdyn);

    if (tid < 128) bias_s[tid] = bias[ncol0 + tid];

    // --- cp.async: thread -> (row, 16B seg); 64B of fp16 per row per chunk ---
    const int rloc = tid >> 2;                 // 0..127
    const int seg  = tid & 3;                  // 0..3
    const int arow = idx[m0 + rloc];
    const __half* pa = g_emb_h + (size_t)arow * EMBED + seg * 8;
    const __half* pb = g_W_h + (size_t)msel * HIDDEN * EMBED
                     + (size_t)(ncol0 + rloc) * EMBED + seg * 8;
    const uint32_t dloc = (uint32_t)(rloc * ROWB + seg * 16);

    auto issue = [&](int k) {
        const uint32_t d0 = smb + (uint32_t)(k & (NSTAGE - 1)) * STAGEB + dloc;
        const int ke = k * 32;
        cpa16(d0 + 0 * TILEB, pa + ke);
        cpa16(d0 + 1 * TILEB, pb + ke);
        CP_COMMIT();
    };

    // --- ldmatrix base addresses (per warp) ---
    const int w_m = w & 3;
    const int w_n = w >> 2;
    const int lrow = lane & 15;
    const int lhalf = (lane >> 4) * 16;
    uint32_t aBase[2], bBase[2];
#pragma unroll
    for (int mt = 0; mt < 2; mt++)
        aBase[mt] = smb + (uint32_t)((w_m * 32 + mt * 16 + lrow) * ROWB + lhalf);
#pragma unroll
    for (int g = 0; g < 2; g++)
        bBase[g] = smb + TILEB + (uint32_t)((w_n * 32 + g * 16 + lrow) * ROWB + lhalf);

    float acc[2][4][4];
#pragma unroll
    for (int mt = 0; mt < 2; mt++)
#pragma unroll
        for (int f = 0; f < 4; f++)
#pragma unroll
            for (int q = 0; q < 4; q++) acc[mt][f][q] = 0.0f;

    // prologue: stages 0..2 in flight (groups 0,1,2)
    issue(0); issue(1); issue(2);

#pragma unroll 1
    for (int k = 0; k < 16; k++) {
        CP_WAIT(2);              // group k complete -> stage k resident
        __syncthreads();         // all warps done reading buffer (k-1)&3
        if (k + 3 < 16) issue(k + 3);   // writes buffer (k-1)&3
        else            CP_COMMIT();    // empty group keeps CP_WAIT(2) exact

        const uint32_t boff = (uint32_t)(k & (NSTAGE - 1)) * STAGEB;
#pragma unroll
        for (int ks = 0; ks < 2; ks++) {
            const uint32_t off = boff + ks * 32;
            uint32_t a[2][4], b[2][4];
#pragma unroll
            for (int mt = 0; mt < 2; mt++)
                ldm4(a[mt][0], a[mt][1], a[mt][2], a[mt][3], aBase[mt] + off);
#pragma unroll
            for (int g = 0; g < 2; g++)
                ldm4(b[g][0], b[g][1], b[g][2], b[g][3], bBase[g] + off);
#pragma unroll
            for (int mt = 0; mt < 2; mt++)
#pragma unroll
                for (int g = 0; g < 2; g++)
#pragma unroll
                    for (int j = 0; j < 2; j++)
                        mma16816(acc[mt][g * 2 + j],
                                 a[mt][0], a[mt][1], a[mt][2], a[mt][3],
                                 b[g][j], b[g][j + 2]);
        }
    }

    // --- epilogue ---
#pragma unroll
    for (int mt = 0; mt < 2; mt++) {
        const int r0 = m0 + w_m * 32 + mt * 16 + (lane >> 2);
#pragma unroll
        for (int g = 0; g < 2; g++)
#pragma unroll
            for (int j = 0; j < 2; j++) {
                const int cl = w_n * 32 + g * 16 + j * 8 + (lane & 3) * 2;
                const float* d = acc[mt][g * 2 + j];
                const float b0 = bias_s[cl], b1 = bias_s[cl + 1];
                if (CoutH) {
                    __half2 v0 = __floats2half2_rn(d[0] + b0, d[1] + b1);
                    __half2 v1 = __floats2half2_rn(d[2] + b0, d[3] + b1);
                    *(__half2*)(CoutH + (size_t)r0 * HIDDEN + ncol0 + cl)       = v0;
                    *(__half2*)(CoutH + (size_t)(r0 + 8) * HIDDEN + ncol0 + cl) = v1;
                } else {
                    float2 v0 = make_float2(d[0] + b0, d[1] + b1);
                    float2 v1 = make_float2(d[2] + b0, d[3] + b1);
                    *(float2*)(CoutF + (size_t)r0 * HIDDEN + ncol0 + cl)       = v0;
                    *(float2*)(CoutF + (size_t)(r0 + 8) * HIDDEN + ncol0 + cl) = v1;
                }
            }
    }
}

// ---------------- attention (fp16 K/V, fp32 Q) ----------------
__global__ __launch_bounds__(256) void attn_kernel(float* __restrict__ out_ctx)
{
    const int b   = blockIdx.x;
    const int tid = threadIdx.x;

    __shared__ float Qs[HEADS][DHEAD];
    __shared__ float Sc[SEQ * HEADS][17];
    __shared__ float Vs[2][SEQ * DHEAD];

    ((float4*)Qs)[tid] = ((const float4*)(g_Q + (size_t)b * HIDDEN))[tid];
    __syncthreads();

    {
        const int s = tid >> 4, g = tid & 15;
        const uint2* krow =
            (const uint2*)(g_Kh + ((size_t)b * SEQ + s) * HIDDEN + g * DHEAD);
        float acc[16];
#pragma unroll
        for (int h = 0; h < 16; h++) acc[h] = 0.0f;
#pragma unroll
        for (int d4 = 0; d4 < 16; d4++) {
            uint2 raw = krow[d4];
            float2 f0 = __half22float2(*(__half2*)&raw.x);
            float2 f1 = __half22float2(*(__half2*)&raw.y);
#pragma unroll
            for (int h = 0; h < 16; h++) {
                float4 qv = *(const float4*)&Qs[h][d4 * 4];
                acc[h] += f0.x * qv.x + f0.y * qv.y + f1.x * qv.z + f1.y * qv.w;
            }
        }
#pragma unroll
        for (int h = 0; h < 16; h++) Sc[s * 16 + h][g] = acc[h] * 0.125f;
    }
    __syncthreads();

    {
        float v[16];
        float* row = Sc[tid];
        float mx = -1e30f;
#pragma unroll
        for (int g = 0; g < 16; g++) { v[g] = row[g]; mx = fmaxf(mx, v[g]); }
        float sum = 0.0f;
#pragma unroll
        for (int g = 0; g < 16; g++) { v[g] = __expf(v[g] - mx); sum += v[g]; }
        float inv = 1.0f / sum;
#pragma unroll
        for (int g = 0; g < 16; g++) row[g] = v[g] * inv;
    }
    __syncthreads();

    const int h  = tid >> 4;
    const int dq = tid & 15;
    float4 acc = make_float4(0.f, 0.f, 0.f, 0.f);
#pragma unroll 1
    for (int s = 0; s < SEQ; s++) {
        float* vbuf = Vs[s & 1];
        {
            uint2 raw = ((const uint2*)(g_Vh + ((size_t)b * SEQ + s) * HIDDEN))[tid];
            float2 f0 = __half22float2(*(__half2*)&raw.x);
            float2 f1 = __half22float2(*(__half2*)&raw.y);
            ((float4*)vbuf)[tid] = make_float4(f0.x, f0.y, f1.x, f1.y);
        }
        __syncthreads();
        const float* arow = Sc[s * 16 + h];
#pragma unroll
        for (int g = 0; g < 16; g++) {
            float a = arow[g];
            float4 v = ((const float4*)vbuf)[g * 16 + dq];
            acc.x = fmaf(a, v.x, acc.x);
            acc.y = fmaf(a, v.y, acc.y);
            acc.z = fmaf(a, v.z, acc.z);
            acc.w = fmaf(a, v.w, acc.w);
        }
    }
    *(float4*)(out_ctx + (size_t)b * HIDDEN + h * DHEAD + dq * 4) = acc;
}

// ---------------------------------------------------------------------------
extern "C" void kernel_launch(void* const* d_in, const int* in_sizes, int n_in,
                              void* d_out, int out_size)
{
    const int*   t   = (const int*)d_in[0];
    const int*   c   = (const int*)d_in[1];
    const float* emb = (const float*)d_in[2];
    const float* WQ  = (const float*)d_in[3];
    const float* bQ  = (const float*)d_in[4];
    const float* WK  = (const float*)d_in[5];
    const float* bK  = (const float*)d_in[6];
    const float* WV  = (const float*)d_in[7];
    const float* bV  = (const float*)d_in[8];
    float* out = (float*)d_out;

    float* out_target = out;
    float* out_ctx    = out + (size_t)BATCH * HIDDEN;

    // fp32 -> fp16 converts
    {
        int n4e = (VOCAB * EMBED) / 4;
        conv_kernel<<<(n4e + 255) / 256, 256>>>(emb, 0, n4e);
        int n4w = (HIDDEN * EMBED) / 4;
        conv_kernel<<<(n4w + 255) / 256, 256>>>(WQ, 1, n4w);
        conv_kernel<<<(n4w + 255) / 256, 256>>>(WK, 2, n4w);
        conv_kernel<<<(n4w + 255) / 256, 256>>>(WV, 3, n4w);
    }

    // tensor-core GEMMs (fp16 mma.sync, 4-stage pipeline)
    cudaFuncSetAttribute(gemm_mma_kernel,
                         cudaFuncAttributeMaxDynamicSharedMemorySize, SMEM_DYN);
    {
        dim3 grid(16, 544);
        gemm_mma_kernel<<<grid, 512, SMEM_DYN>>>(t, c, bQ, bK, bV, out_target);
    }

    // attention -> context_vector
    attn_kernel<<<BATCH, 256>>>(out_ctx);
}

// round 6
// speedup vs baseline: 3.7766x; 1.0591x over previous
#include <cuda_runtime.h>
#include <cuda_fp16.h>
#include <cstdint>

#define BATCH  4096
#define SEQ    16
#define EMBED  512
#define HIDDEN 1024
#define HEADS  16
#define DHEAD  64
#define VOCAB  50257

// ---------------- device scratch (no cudaMalloc allowed) ----------------
__device__ float  g_Q[(size_t)BATCH * HIDDEN];                   // 16 MB (fp32)
__device__ __half g_Kh[(size_t)BATCH * SEQ * HIDDEN];            // 128 MB
__device__ __half g_Vh[(size_t)BATCH * SEQ * HIDDEN];            // 128 MB
__device__ __half g_emb_h[(size_t)VOCAB * EMBED];                // ~49 MB
__device__ __half g_W_h[3u * HIDDEN * EMBED];                    // WQ,WK,WV fp16

// ---------------- helpers ----------------
__device__ __forceinline__ uint32_t smem_u32(const void* p) {
    uint32_t a;
    asm("{ .reg .u64 t; cvta.to.shared.u64 t, %1; cvt.u32.u64 %0, t; }"
        : "=r"(a) : "l"(p));
    return a;
}
__device__ __forceinline__ void cpa16(uint32_t dst, const void* src) {
    asm volatile("cp.async.cg.shared.global [%0], [%1], 16;"
                 :: "r"(dst), "l"(src) : "memory");
}
#define CP_COMMIT() asm volatile("cp.async.commit_group;" ::: "memory")
#define CP_WAIT(n)  asm volatile("cp.async.wait_group %0;" :: "n"(n) : "memory")

__device__ __forceinline__ void ldm4(uint32_t& r0, uint32_t& r1,
                                     uint32_t& r2, uint32_t& r3, uint32_t a) {
    asm volatile("ldmatrix.sync.aligned.m8n8.x4.shared.b16 {%0,%1,%2,%3}, [%4];"
                 : "=r"(r0), "=r"(r1), "=r"(r2), "=r"(r3) : "r"(a));
}
__device__ __forceinline__ void mma16816(float* d,
                                         uint32_t a0, uint32_t a1, uint32_t a2, uint32_t a3,
                                         uint32_t b0, uint32_t b1) {
    asm volatile(
        "mma.sync.aligned.m16n8k16.row.col.f32.f16.f16.f32 "
        "{%0,%1,%2,%3}, {%4,%5,%6,%7}, {%8,%9}, {%0,%1,%2,%3};"
        : "+f"(d[0]), "+f"(d[1]), "+f"(d[2]), "+f"(d[3])
        : "r"(a0), "r"(a1), "r"(a2), "r"(a3), "r"(b0), "r"(b1));
}

// ---------------- fp32 -> fp16 convert ----------------
__global__ __launch_bounds__(256) void conv_kernel(const float* __restrict__ src,
                                                   int dst_sel, int n4) {
    int i = blockIdx.x * blockDim.x + threadIdx.x;
    if (i >= n4) return;
    __half* dst = (dst_sel == 0) ? g_emb_h
                                 : g_W_h + (size_t)(dst_sel - 1) * HIDDEN * EMBED;
    float4 v = ((const float4*)src)[i];
    ((__half2*)dst)[2 * i]     = __floats2half2_rn(v.x, v.y);
    ((__half2*)dst)[2 * i + 1] = __floats2half2_rn(v.z, v.w);
}

// ---------------- mma.sync gathered GEMM (fp16, 128x256 tile) ----------------
// CTA tile 128x256, K chunks of 32, 4 cp.async stages, 1 barrier per chunk.
// 512 threads = 16 warps (4 M x 4 N), warp tile 32x64.
// grid = (8, 544): by<512 -> context rows (idx=c), else target rows (idx=t).
// nt<4 -> WQ/WK col tile nt, nt>=4 -> WV col tile nt-4.  ncol0 = (nt&3)*256.
#define ROWB    80                      // smem row stride bytes (64 B data + 16 pad)
#define TILEA   (128 * ROWB)            // 10240 B
#define TILEBB  (256 * ROWB)            // 20480 B
#define STAGEB  (TILEA + TILEBB)        // 30720 B
#define NSTAGE  4
#define SMEM_DYN (NSTAGE * STAGEB)      // 122880 B

__global__ __launch_bounds__(512, 1) void gemm_mma_kernel(
    const int* __restrict__ t, const int* __restrict__ c,
    const float* __restrict__ bQ, const float* __restrict__ bK,
    const float* __restrict__ bV, float* __restrict__ out_target)
{
    extern __shared__ char smdyn[];
    __shared__ float bias_s[256];

    const int tid  = threadIdx.x;
    const int lane = tid & 31;
    const int w    = tid >> 5;

    const int  nt   = blockIdx.x;              // 0..7
    const int  by   = blockIdx.y;              // 0..543
    const bool is_t = (by >= 512);
    const int  m0   = (is_t ? by - 512 : by) * 128;
    const int* idx  = is_t ? t : c;
    const int  msel = (nt < 4) ? (is_t ? 0 : 1) : 2;   // WQ / WK / WV
    const float* bias = (nt < 4) ? (is_t ? bQ : bK) : bV;
    float*  CoutF = is_t ? ((nt < 4) ? g_Q : out_target) : nullptr;
    __half* CoutH = is_t ? nullptr : ((nt < 4) ? g_Kh : g_Vh);
    const int ncol0 = (nt & 3) * 256;

    const uint32_t smb = smem_u32(smdyn);

    if (tid < 256) bias_s[tid] = bias[ncol0 + tid];

    // --- cp.async assignments ---
    // A: 128 rows x 4 segs (16B) -> 1 per thread
    const int rA = tid >> 2;
    const int sA = tid & 3;
    const int arow = idx[m0 + rA];
    const __half* pa = g_emb_h + (size_t)arow * EMBED + sA * 8;
    const uint32_t dA = (uint32_t)(rA * ROWB + sA * 16);
    // B: 256 rows x 4 segs -> 2 per thread (consecutive segs)
    const int rB = tid >> 1;
    const int sB = (tid & 1) * 2;
    const __half* pb = g_W_h + (size_t)msel * HIDDEN * EMBED
                     + (size_t)(ncol0 + rB) * EMBED + sB * 8;
    const uint32_t dB = (uint32_t)(rB * ROWB + sB * 16);

    auto issue = [&](int k) {
        const uint32_t d0 = smb + (uint32_t)(k & (NSTAGE - 1)) * STAGEB;
        const int ke = k * 32;
        cpa16(d0 + dA, pa + ke);
        cpa16(d0 + TILEA + dB,      pb + ke);
        cpa16(d0 + TILEA + dB + 16, pb + ke + 8);
        CP_COMMIT();
    };

    // --- ldmatrix base addresses (per warp) ---
    const int w_m = w & 3;                     // M block of 32
    const int w_n = w >> 2;                    // N block of 64
    const int lrow = lane & 15;
    const int lhalf = (lane >> 4) * 16;
    uint32_t aBase[2], bBase[4];
#pragma unroll
    for (int mt = 0; mt < 2; mt++)
        aBase[mt] = smb + (uint32_t)((w_m * 32 + mt * 16 + lrow) * ROWB + lhalf);
#pragma unroll
    for (int g = 0; g < 4; g++)
        bBase[g] = smb + TILEA + (uint32_t)((w_n * 64 + g * 16 + lrow) * ROWB + lhalf);

    float acc[2][8][4];
#pragma unroll
    for (int mt = 0; mt < 2; mt++)
#pragma unroll
        for (int f = 0; f < 8; f++)
#pragma unroll
            for (int q = 0; q < 4; q++) acc[mt][f][q] = 0.0f;

    // prologue: stages 0..2 in flight
    issue(0); issue(1); issue(2);

#pragma unroll 1
    for (int k = 0; k < 16; k++) {
        CP_WAIT(2);              // group k complete -> stage k resident
        __syncthreads();         // all warps done reading buffer (k-1)&3
        if (k + 3 < 16) issue(k + 3);
        else            CP_COMMIT();    // empty group keeps CP_WAIT(2) exact

        const uint32_t boff = (uint32_t)(k & (NSTAGE - 1)) * STAGEB;
#pragma unroll
        for (int ks = 0; ks < 2; ks++) {
            const uint32_t off = boff + ks * 32;
            uint32_t a[2][4], b[4][4];
#pragma unroll
            for (int mt = 0; mt < 2; mt++)
                ldm4(a[mt][0], a[mt][1], a[mt][2], a[mt][3], aBase[mt] + off);
#pragma unroll
            for (int g = 0; g < 4; g++)
                ldm4(b[g][0], b[g][1], b[g][2], b[g][3], bBase[g] + off);
#pragma unroll
            for (int mt = 0; mt < 2; mt++)
#pragma unroll
                for (int g = 0; g < 4; g++)
#pragma unroll
                    for (int j = 0; j < 2; j++)
                        mma16816(acc[mt][g * 2 + j],
                                 a[mt][0], a[mt][1], a[mt][2], a[mt][3],
                                 b[g][j], b[g][j + 2]);
        }
    }

    // --- epilogue ---
#pragma unroll
    for (int mt = 0; mt < 2; mt++) {
        const int r0 = m0 + w_m * 32 + mt * 16 + (lane >> 2);
#pragma unroll
        for (int g = 0; g < 4; g++)
#pragma unroll
            for (int j = 0; j < 2; j++) {
                const int cl = w_n * 64 + g * 16 + j * 8 + (lane & 3) * 2;
                const float* d = acc[mt][g * 2 + j];
                const float b0 = bias_s[cl], b1 = bias_s[cl + 1];
                if (CoutH) {
                    __half2 v0 = __floats2half2_rn(d[0] + b0, d[1] + b1);
                    __half2 v1 = __floats2half2_rn(d[2] + b0, d[3] + b1);
                    *(__half2*)(CoutH + (size_t)r0 * HIDDEN + ncol0 + cl)       = v0;
                    *(__half2*)(CoutH + (size_t)(r0 + 8) * HIDDEN + ncol0 + cl) = v1;
                } else {
                    float2 v0 = make_float2(d[0] + b0, d[1] + b1);
                    float2 v1 = make_float2(d[2] + b0, d[3] + b1);
                    *(float2*)(CoutF + (size_t)r0 * HIDDEN + ncol0 + cl)       = v0;
                    *(float2*)(CoutF + (size_t)(r0 + 8) * HIDDEN + ncol0 + cl) = v1;
                }
            }
    }
}

// ---------------- attention (fp16 K/V, fp32 Q) ----------------
__global__ __launch_bounds__(256) void attn_kernel(float* __restrict__ out_ctx)
{
    const int b   = blockIdx.x;
    const int tid = threadIdx.x;

    __shared__ float Qs[HEADS][DHEAD];
    __shared__ float Sc[SEQ * HEADS][17];
    __shared__ float Vs[2][SEQ * DHEAD];

    ((float4*)Qs)[tid] = ((const float4*)(g_Q + (size_t)b * HIDDEN))[tid];
    __syncthreads();

    {
        const int s = tid >> 4, g = tid & 15;
        const uint2* krow =
            (const uint2*)(g_Kh + ((size_t)b * SEQ + s) * HIDDEN + g * DHEAD);
        float acc[16];
#pragma unroll
        for (int h = 0; h < 16; h++) acc[h] = 0.0f;
#pragma unroll
        for (int d4 = 0; d4 < 16; d4++) {
            uint2 raw = krow[d4];
            float2 f0 = __half22float2(*(__half2*)&raw.x);
            float2 f1 = __half22float2(*(__half2*)&raw.y);
#pragma unroll
            for (int h = 0; h < 16; h++) {
                float4 qv = *(const float4*)&Qs[h][d4 * 4];
                acc[h] += f0.x * qv.x + f0.y * qv.y + f1.x * qv.z + f1.y * qv.w;
            }
        }
#pragma unroll
        for (int h = 0; h < 16; h++) Sc[s * 16 + h][g] = acc[h] * 0.125f;
    }
    __syncthreads();

    {
        float v[16];
        float* row = Sc[tid];
        float mx = -1e30f;
#pragma unroll
        for (int g = 0; g < 16; g++) { v[g] = row[g]; mx = fmaxf(mx, v[g]); }
        float sum = 0.0f;
#pragma unroll
        for (int g = 0; g < 16; g++) { v[g] = __expf(v[g] - mx); sum += v[g]; }
        float inv = 1.0f / sum;
#pragma unroll
        for (int g = 0; g < 16; g++) row[g] = v[g] * inv;
    }
    __syncthreads();

    const int h  = tid >> 4;
    const int dq = tid & 15;
    float4 acc = make_float4(0.f, 0.f, 0.f, 0.f);
#pragma unroll 1
    for (int s = 0; s < SEQ; s++) {
        float* vbuf = Vs[s & 1];
        {
            uint2 raw = ((const uint2*)(g_Vh + ((size_t)b * SEQ + s) * HIDDEN))[tid];
            float2 f0 = __half22float2(*(__half2*)&raw.x);
            float2 f1 = __half22float2(*(__half2*)&raw.y);
            ((float4*)vbuf)[tid] = make_float4(f0.x, f0.y, f1.x, f1.y);
        }
        __syncthreads();
        const float* arow = Sc[s * 16 + h];
#pragma unroll
        for (int g = 0; g < 16; g++) {
            float a = arow[g];
            float4 v = ((const float4*)vbuf)[g * 16 + dq];
            acc.x = fmaf(a, v.x, acc.x);
            acc.y = fmaf(a, v.y, acc.y);
            acc.z = fmaf(a, v.z, acc.z);
            acc.w = fmaf(a, v.w, acc.w);
        }
    }
    *(float4*)(out_ctx + (size_t)b * HIDDEN + h * DHEAD + dq * 4) = acc;
}

// ---------------------------------------------------------------------------
extern "C" void kernel_launch(void* const* d_in, const int* in_sizes, int n_in,
                              void* d_out, int out_size)
{
    const int*   t   = (const int*)d_in[0];
    const int*   c   = (const int*)d_in[1];
    const float* emb = (const float*)d_in[2];
    const float* WQ  = (const float*)d_in[3];
    const float* bQ  = (const float*)d_in[4];
    const float* WK  = (const float*)d_in[5];
    const float* bK  = (const float*)d_in[6];
    const float* WV  = (const float*)d_in[7];
    const float* bV  = (const float*)d_in[8];
    float* out = (float*)d_out;

    float* out_target = out;
    float* out_ctx    = out + (size_t)BATCH * HIDDEN;

    // fp32 -> fp16 converts
    {
        int n4e = (VOCAB * EMBED) / 4;
        conv_kernel<<<(n4e + 255) / 256, 256>>>(emb, 0, n4e);
        int n4w = (HIDDEN * EMBED) / 4;
        conv_kernel<<<(n4w + 255) / 256, 256>>>(WQ, 1, n4w);
        conv_kernel<<<(n4w + 255) / 256, 256>>>(WK, 2, n4w);
        conv_kernel<<<(n4w + 255) / 256, 256>>>(WV, 3, n4w);
    }

    // tensor-core GEMMs (fp16 mma.sync, 128x256 tiles, 4-stage pipeline)
    cudaFuncSetAttribute(gemm_mma_kernel,
                         cudaFuncAttributeMaxDynamicSharedMemorySize, SMEM_DYN);
    {
        dim3 grid(8, 544);
        gemm_mma_kernel<<<grid, 512, SMEM_DYN>>>(t, c, bQ, bK, bV, out_target);
    }

    // attention -> context_vector
    attn_kernel<<<BATCH, 256>>>(out_ctx);
}

// round 7
// speedup vs baseline: 3.8561x; 1.0210x over previous
#include <cuda_runtime.h>
#include <cuda_fp16.h>
#include <cstdint>

#define BATCH  4096
#define SEQ    16
#define EMBED  512
#define HIDDEN 1024
#define HEADS  16
#define DHEAD  64
#define VOCAB  50257

// ---------------- device scratch (no cudaMalloc allowed) ----------------
__device__ float  g_Q[(size_t)BATCH * HIDDEN];                   // 16 MB (fp32)
__device__ __half g_Kh[(size_t)BATCH * SEQ * HIDDEN];            // 128 MB
__device__ __half g_Vh[(size_t)BATCH * SEQ * HIDDEN];            // 128 MB
__device__ __half g_emb_h[(size_t)VOCAB * EMBED];                // ~49 MB
__device__ __half g_W_h[3u * HIDDEN * EMBED];                    // WQ,WK,WV fp16

// ---------------- helpers ----------------
__device__ __forceinline__ uint32_t smem_u32(const void* p) {
    uint32_t a;
    asm("{ .reg .u64 t; cvta.to.shared.u64 t, %1; cvt.u32.u64 %0, t; }"
        : "=r"(a) : "l"(p));
    return a;
}
__device__ __forceinline__ void cpa16(uint32_t dst, const void* src) {
    asm volatile("cp.async.cg.shared.global [%0], [%1], 16;"
                 :: "r"(dst), "l"(src) : "memory");
}
#define CP_COMMIT() asm volatile("cp.async.commit_group;" ::: "memory")
#define CP_WAIT(n)  asm volatile("cp.async.wait_group %0;" :: "n"(n) : "memory")

__device__ __forceinline__ void ldm4(uint32_t& r0, uint32_t& r1,
                                     uint32_t& r2, uint32_t& r3, uint32_t a) {
    asm volatile("ldmatrix.sync.aligned.m8n8.x4.shared.b16 {%0,%1,%2,%3}, [%4];"
                 : "=r"(r0), "=r"(r1), "=r"(r2), "=r"(r3) : "r"(a));
}
__device__ __forceinline__ void mma16816(float* d,
                                         uint32_t a0, uint32_t a1, uint32_t a2, uint32_t a3,
                                         uint32_t b0, uint32_t b1) {
    asm volatile(
        "mma.sync.aligned.m16n8k16.row.col.f32.f16.f16.f32 "
        "{%0,%1,%2,%3}, {%4,%5,%6,%7}, {%8,%9}, {%0,%1,%2,%3};"
        : "+f"(d[0]), "+f"(d[1]), "+f"(d[2]), "+f"(d[3])
        : "r"(a0), "r"(a1), "r"(a2), "r"(a3), "r"(b0), "r"(b1));
}

// ---------------- fp32 -> fp16 convert ----------------
__global__ __launch_bounds__(256) void conv_kernel(const float* __restrict__ src,
                                                   int dst_sel, int n4) {
    int i = blockIdx.x * blockDim.x + threadIdx.x;
    if (i >= n4) return;
    __half* dst = (dst_sel == 0) ? g_emb_h
                                 : g_W_h + (size_t)(dst_sel - 1) * HIDDEN * EMBED;
    float4 v = ((const float4*)src)[i];
    ((__half2*)dst)[2 * i]     = __floats2half2_rn(v.x, v.y);
    ((__half2*)dst)[2 * i + 1] = __floats2half2_rn(v.z, v.w);
}

// ---------------- mma.sync gathered GEMM (fp16, 128x128 tile, occ 2) --------
// CTA tile 128x128, K chunks of 32, 4 cp.async stages, 1 barrier per chunk.
// 256 threads = 8 warps (4 M x 2 N), warp tile 32x64. 2 CTAs/SM.
// grid = (16, 544): by<512 -> context rows (idx=c), else target rows (idx=t).
#define ROWB    80                      // smem row stride bytes (64 B data + 16 pad)
#define TILEX   (128 * ROWB)            // 10240 B per matrix per stage
#define STAGEB  (2 * TILEX)             // 20480 B
#define NSTAGE  4
#define SMEM_DYN (NSTAGE * STAGEB)      // 81920 B per CTA

__global__ __launch_bounds__(256, 2) void gemm_mma_kernel(
    const int* __restrict__ t, const int* __restrict__ c,
    const float* __restrict__ bQ, const float* __restrict__ bK,
    const float* __restrict__ bV, float* __restrict__ out_target)
{
    extern __shared__ char smdyn[];
    __shared__ float bias_s[128];

    const int tid  = threadIdx.x;
    const int lane = tid & 31;
    const int w    = tid >> 5;

    const int  nt   = blockIdx.x;              // 0..15
    const int  by   = blockIdx.y;              // 0..543
    const bool is_t = (by >= 512);
    const int  m0   = (is_t ? by - 512 : by) * 128;
    const int* idx  = is_t ? t : c;
    const int  msel = (nt < 8) ? (is_t ? 0 : 1) : 2;   // WQ / WK / WV
    const float* bias = (nt < 8) ? (is_t ? bQ : bK) : bV;
    float*  CoutF = is_t ? ((nt < 8) ? g_Q : out_target) : nullptr;
    __half* CoutH = is_t ? nullptr : ((nt < 8) ? g_Kh : g_Vh);
    const int ncol0 = (nt & 7) * 128;

    const uint32_t smb = smem_u32(smdyn);

    if (tid < 128) bias_s[tid] = bias[ncol0 + tid];

    // --- cp.async: 128 rows x 4 segs(16B) per matrix; 256 thr -> 2 segs each ---
    const int rr = tid >> 1;                   // 0..127
    const int ss = (tid & 1) * 2;              // seg pair 0 or 2
    const int arow = idx[m0 + rr];
    const __half* pa = g_emb_h + (size_t)arow * EMBED + ss * 8;
    const __half* pb = g_W_h + (size_t)msel * HIDDEN * EMBED
                     + (size_t)(ncol0 + rr) * EMBED + ss * 8;
    const uint32_t dd = (uint32_t)(rr * ROWB + ss * 16);

    auto issue = [&](int k) {
        const uint32_t d0 = smb + (uint32_t)(k & (NSTAGE - 1)) * STAGEB + dd;
        const int ke = k * 32;
        cpa16(d0,              pa + ke);
        cpa16(d0 + 16,         pa + ke + 8);
        cpa16(d0 + TILEX,      pb + ke);
        cpa16(d0 + TILEX + 16, pb + ke + 8);
        CP_COMMIT();
    };

    // --- ldmatrix base addresses (per warp): 8 warps = 4 M x 2 N ---
    const int w_m = w & 3;                     // M block of 32
    const int w_n = w >> 2;                    // N block of 64 (0..1)
    const int lrow = lane & 15;
    const int lhalf = (lane >> 4) * 16;
    uint32_t aBase[2], bBase[4];
#pragma unroll
    for (int mt = 0; mt < 2; mt++)
        aBase[mt] = smb + (uint32_t)((w_m * 32 + mt * 16 + lrow) * ROWB + lhalf);
#pragma unroll
    for (int g = 0; g < 4; g++)
        bBase[g] = smb + TILEX + (uint32_t)((w_n * 64 + g * 16 + lrow) * ROWB + lhalf);

    float acc[2][8][4];
#pragma unroll
    for (int mt = 0; mt < 2; mt++)
#pragma unroll
        for (int f = 0; f < 8; f++)
#pragma unroll
            for (int q = 0; q < 4; q++) acc[mt][f][q] = 0.0f;

    // prologue: stages 0..2 in flight
    issue(0); issue(1); issue(2);

#pragma unroll 1
    for (int k = 0; k < 16; k++) {
        CP_WAIT(2);              // group k complete -> stage k resident
        __syncthreads();         // all warps done reading buffer (k-1)&3
        if (k + 3 < 16) issue(k + 3);
        else            CP_COMMIT();    // empty group keeps CP_WAIT(2) exact

        const uint32_t boff = (uint32_t)(k & (NSTAGE - 1)) * STAGEB;
#pragma unroll
        for (int ks = 0; ks < 2; ks++) {
            const uint32_t off = boff + ks * 32;
            uint32_t a[2][4], b[4][4];
#pragma unroll
            for (int mt = 0; mt < 2; mt++)
                ldm4(a[mt][0], a[mt][1], a[mt][2], a[mt][3], aBase[mt] + off);
#pragma unroll
            for (int g = 0; g < 4; g++)
                ldm4(b[g][0], b[g][1], b[g][2], b[g][3], bBase[g] + off);
#pragma unroll
            for (int mt = 0; mt < 2; mt++)
#pragma unroll
                for (int g = 0; g < 4; g++)
#pragma unroll
                    for (int j = 0; j < 2; j++)
                        mma16816(acc[mt][g * 2 + j],
                                 a[mt][0], a[mt][1], a[mt][2], a[mt][3],
                                 b[g][j], b[g][j + 2]);
        }
    }

    // --- epilogue ---
#pragma unroll
    for (int mt = 0; mt < 2; mt++) {
        const int r0 = m0 + w_m * 32 + mt * 16 + (lane >> 2);
#pragma unroll
        for (int g = 0; g < 4; g++)
#pragma unroll
            for (int j = 0; j < 2; j++) {
                const int cl = w_n * 64 + g * 16 + j * 8 + (lane & 3) * 2;
                const float* d = acc[mt][g * 2 + j];
                const float b0 = bias_s[cl], b1 = bias_s[cl + 1];
                if (CoutH) {
                    __half2 v0 = __floats2half2_rn(d[0] + b0, d[1] + b1);
                    __half2 v1 = __floats2half2_rn(d[2] + b0, d[3] + b1);
                    *(__half2*)(CoutH + (size_t)r0 * HIDDEN + ncol0 + cl)       = v0;
                    *(__half2*)(CoutH + (size_t)(r0 + 8) * HIDDEN + ncol0 + cl) = v1;
                } else {
                    float2 v0 = make_float2(d[0] + b0, d[1] + b1);
                    float2 v1 = make_float2(d[2] + b0, d[3] + b1);
                    *(float2*)(CoutF + (size_t)r0 * HIDDEN + ncol0 + cl)       = v0;
                    *(float2*)(CoutF + (size_t)(r0 + 8) * HIDDEN + ncol0 + cl) = v1;
                }
            }
    }
}

// ---------------- attention (fp16 K/V, fp32 Q) ----------------
__global__ __launch_bounds__(256) void attn_kernel(float* __restrict__ out_ctx)
{
    const int b   = blockIdx.x;
    const int tid = threadIdx.x;

    __shared__ float Qs[HEADS][DHEAD];
    __shared__ float Sc[SEQ * HEADS][17];
    __shared__ float Vs[2][SEQ * DHEAD];

    ((float4*)Qs)[tid] = ((const float4*)(g_Q + (size_t)b * HIDDEN))[tid];
    __syncthreads();

    {
        const int s = tid >> 4, g = tid & 15;
        const uint2* krow =
            (const uint2*)(g_Kh + ((size_t)b * SEQ + s) * HIDDEN + g * DHEAD);
        float acc[16];
#pragma unroll
        for (int h = 0; h < 16; h++) acc[h] = 0.0f;
#pragma unroll
        for (int d4 = 0; d4 < 16; d4++) {
            uint2 raw = krow[d4];
            float2 f0 = __half22float2(*(__half2*)&raw.x);
            float2 f1 = __half22float2(*(__half2*)&raw.y);
#pragma unroll
            for (int h = 0; h < 16; h++) {
                float4 qv = *(const float4*)&Qs[h][d4 * 4];
                acc[h] += f0.x * qv.x + f0.y * qv.y + f1.x * qv.z + f1.y * qv.w;
            }
        }
#pragma unroll
        for (int h = 0; h < 16; h++) Sc[s * 16 + h][g] = acc[h] * 0.125f;
    }
    __syncthreads();

    {
        float v[16];
        float* row = Sc[tid];
        float mx = -1e30f;
#pragma unroll
        for (int g = 0; g < 16; g++) { v[g] = row[g]; mx = fmaxf(mx, v[g]); }
        float sum = 0.0f;
#pragma unroll
        for (int g = 0; g < 16; g++) { v[g] = __expf(v[g] - mx); sum += v[g]; }
        float inv = 1.0f / sum;
#pragma unroll
        for (int g = 0; g < 16; g++) row[g] = v[g] * inv;
    }
    __syncthreads();

    const int h  = tid >> 4;
    const int dq = tid & 15;
    float4 acc = make_float4(0.f, 0.f, 0.f, 0.f);
#pragma unroll 1
    for (int s = 0; s < SEQ; s++) {
        float* vbuf = Vs[s & 1];
        {
            uint2 raw = ((const uint2*)(g_Vh + ((size_t)b * SEQ + s) * HIDDEN))[tid];
            float2 f0 = __half22float2(*(__half2*)&raw.x);
            float2 f1 = __half22float2(*(__half2*)&raw.y);
            ((float4*)vbuf)[tid] = make_float4(f0.x, f0.y, f1.x, f1.y);
        }
        __syncthreads();
        const float* arow = Sc[s * 16 + h];
#pragma unroll
        for (int g = 0; g < 16; g++) {
            float a = arow[g];
            float4 v = ((const float4*)vbuf)[g * 16 + dq];
            acc.x = fmaf(a, v.x, acc.x);
            acc.y = fmaf(a, v.y, acc.y);
            acc.z = fmaf(a, v.z, acc.z);
            acc.w = fmaf(a, v.w, acc.w);
        }
    }
    *(float4*)(out_ctx + (size_t)b * HIDDEN + h * DHEAD + dq * 4) = acc;
}

// ---------------------------------------------------------------------------
extern "C" void kernel_launch(void* const* d_in, const int* in_sizes, int n_in,
                              void* d_out, int out_size)
{
    const int*   t   = (const int*)d_in[0];
    const int*   c   = (const int*)d_in[1];
    const float* emb = (const float*)d_in[2];
    const float* WQ  = (const float*)d_in[3];
    const float* bQ  = (const float*)d_in[4];
    const float* WK  = (const float*)d_in[5];
    const float* bK  = (const float*)d_in[6];
    const float* WV  = (const float*)d_in[7];
    const float* bV  = (const float*)d_in[8];
    float* out = (float*)d_out;

    float* out_target = out;
    float* out_ctx    = out + (size_t)BATCH * HIDDEN;

    // fp32 -> fp16 converts
    {
        int n4e = (VOCAB * EMBED) / 4;
        conv_kernel<<<(n4e + 255) / 256, 256>>>(emb, 0, n4e);
        int n4w = (HIDDEN * EMBED) / 4;
        conv_kernel<<<(n4w + 255) / 256, 256>>>(WQ, 1, n4w);
        conv_kernel<<<(n4w + 255) / 256, 256>>>(WK, 2, n4w);
        conv_kernel<<<(n4w + 255) / 256, 256>>>(WV, 3, n4w);
    }

    // tensor-core GEMMs (fp16 mma.sync, 128x128 tiles, 4-stage pipe, occ 2)
    cudaFuncSetAttribute(gemm_mma_kernel,
                         cudaFuncAttributeMaxDynamicSharedMemorySize, SMEM_DYN);
    {
        dim3 grid(16, 544);
        gemm_mma_kernel<<<grid, 256, SMEM_DYN>>>(t, c, bQ, bK, bV, out_target);
    }

    // attention -> context_vector
    attn_kernel<<<BATCH, 256>>>(out_ctx);
}

// round 8
// speedup vs baseline: 4.5259x; 1.1737x over previous
#include <cuda_runtime.h>
#include <cuda_fp16.h>
#include <cstdint>

#define BATCH  4096
#define SEQ    16
#define EMBED  512
#define HIDDEN 1024
#define HEADS  16
#define DHEAD  64
#define VOCAB  50257
#define VPAD   50304                    // 393 * 128
#define NV_TILES 393
#define NT_TILES 32

// ---------------- device scratch (no cudaMalloc allowed) ----------------
__device__ float  g_Q[(size_t)BATCH * HIDDEN];                   // 16 MB
__device__ __half g_Kv[(size_t)VPAD * HIDDEN];                   // ~103 MB (per-token K)
__device__ __half g_Vv[(size_t)VPAD * HIDDEN];                   // ~103 MB (per-token V)
__device__ __half g_emb_h[(size_t)VPAD * EMBED];                 // padded, pad rows = 0
__device__ __half g_W_h[3u * HIDDEN * EMBED];                    // WQ,WK,WV fp16

// ---------------- helpers ----------------
__device__ __forceinline__ uint32_t smem_u32(const void* p) {
    uint32_t a;
    asm("{ .reg .u64 t; cvta.to.shared.u64 t, %1; cvt.u32.u64 %0, t; }"
        : "=r"(a) : "l"(p));
    return a;
}
__device__ __forceinline__ void cpa16(uint32_t dst, const void* src) {
    asm volatile("cp.async.cg.shared.global [%0], [%1], 16;"
                 :: "r"(dst), "l"(src) : "memory");
}
#define CP_COMMIT() asm volatile("cp.async.commit_group;" ::: "memory")
#define CP_WAIT(n)  asm volatile("cp.async.wait_group %0;" :: "n"(n) : "memory")

__device__ __forceinline__ void ldm4(uint32_t& r0, uint32_t& r1,
                                     uint32_t& r2, uint32_t& r3, uint32_t a) {
    asm volatile("ldmatrix.sync.aligned.m8n8.x4.shared.b16 {%0,%1,%2,%3}, [%4];"
                 : "=r"(r0), "=r"(r1), "=r"(r2), "=r"(r3) : "r"(a));
}
__device__ __forceinline__ void mma16816(float* d,
                                         uint32_t a0, uint32_t a1, uint32_t a2, uint32_t a3,
                                         uint32_t b0, uint32_t b1) {
    asm volatile(
        "mma.sync.aligned.m16n8k16.row.col.f32.f16.f16.f32 "
        "{%0,%1,%2,%3}, {%4,%5,%6,%7}, {%8,%9}, {%0,%1,%2,%3};"
        : "+f"(d[0]), "+f"(d[1]), "+f"(d[2]), "+f"(d[3])
        : "r"(a0), "r"(a1), "r"(a2), "r"(a3), "r"(b0), "r"(b1));
}

// ---------------- fp32 -> fp16 convert ----------------
__global__ __launch_bounds__(256) void conv_kernel(const float* __restrict__ src,
                                                   int dst_sel, int n4) {
    int i = blockIdx.x * blockDim.x + threadIdx.x;
    if (i >= n4) return;
    __half* dst = (dst_sel == 0) ? g_emb_h
                                 : g_W_h + (size_t)(dst_sel - 1) * HIDDEN * EMBED;
    float4 v = ((const float4*)src)[i];
    ((__half2*)dst)[2 * i]     = __floats2half2_rn(v.x, v.y);
    ((__half2*)dst)[2 * i + 1] = __floats2half2_rn(v.z, v.w);
}

// ---------------- fp16 mma.sync GEMM (128x128 tile, occ 2) ------------------
// grid = (16, 425):
//   by <  393: DENSE vocab rows  -> K/V tables (nt<8 -> WK->g_Kv, else WV->g_Vv)
//   by >= 393: gathered t rows   -> fp32 Q (nt<8, WQ) / out_target (WV)
#define ROWB    80
#define TILEX   (128 * ROWB)            // 10240 B
#define STAGEB  (2 * TILEX)             // 20480 B
#define NSTAGE  4
#define SMEM_DYN (NSTAGE * STAGEB)      // 81920 B

__global__ __launch_bounds__(256, 2) void gemm_mma_kernel(
    const int* __restrict__ t,
    const float* __restrict__ bQ, const float* __restrict__ bK,
    const float* __restrict__ bV, float* __restrict__ out_target)
{
    extern __shared__ char smdyn[];
    __shared__ float bias_s[128];

    const int tid  = threadIdx.x;
    const int lane = tid & 31;
    const int w    = tid >> 5;

    const int  nt    = blockIdx.x;             // 0..15
    const int  by    = blockIdx.y;             // 0..424
    const bool is_t  = (by >= NV_TILES);
    const int  m0    = (is_t ? by - NV_TILES : by) * 128;
    const int  msel  = is_t ? ((nt < 8) ? 0 : 2)   // WQ / WV
                            : ((nt < 8) ? 1 : 2);  // WK / WV
    const float* bias = is_t ? ((nt < 8) ? bQ : bV)
                             : ((nt < 8) ? bK : bV);
    float*  CoutF = is_t ? ((nt < 8) ? g_Q : out_target) : nullptr;
    __half* CoutH = is_t ? nullptr : ((nt < 8) ? g_Kv : g_Vv);
    const int ncol0 = (nt & 7) * 128;

    const uint32_t smb = smem_u32(smdyn);

    if (tid < 128) bias_s[tid] = bias[ncol0 + tid];

    // --- cp.async: 128 rows x 4 segs(16B) per matrix; 256 thr -> 2 segs each ---
    const int rr = tid >> 1;                   // 0..127
    const int ss = (tid & 1) * 2;              // seg pair 0 or 2
    const int arow = is_t ? t[m0 + rr] : (m0 + rr);   // dense vocab rows, or gather
    const __half* pa = g_emb_h + (size_t)arow * EMBED + ss * 8;
    const __half* pb = g_W_h + (size_t)msel * HIDDEN * EMBED
                     + (size_t)(ncol0 + rr) * EMBED + ss * 8;
    const uint32_t dd = (uint32_t)(rr * ROWB + ss * 16);

    auto issue = [&](int k) {
        const uint32_t d0 = smb + (uint32_t)(k & (NSTAGE - 1)) * STAGEB + dd;
        const int ke = k * 32;
        cpa16(d0,              pa + ke);
        cpa16(d0 + 16,         pa + ke + 8);
        cpa16(d0 + TILEX,      pb + ke);
        cpa16(d0 + TILEX + 16, pb + ke + 8);
        CP_COMMIT();
    };

    // --- ldmatrix bases: 8 warps = 4 M x 2 N, warp tile 32x64 ---
    const int w_m = w & 3;
    const int w_n = w >> 2;
    const int lrow = lane & 15;
    const int lhalf = (lane >> 4) * 16;
    uint32_t aBase[2], bBase[4];
#pragma unroll
    for (int mt = 0; mt < 2; mt++)
        aBase[mt] = smb + (uint32_t)((w_m * 32 + mt * 16 + lrow) * ROWB + lhalf);
#pragma unroll
    for (int g = 0; g < 4; g++)
        bBase[g] = smb + TILEX + (uint32_t)((w_n * 64 + g * 16 + lrow) * ROWB + lhalf);

    float acc[2][8][4];
#pragma unroll
    for (int mt = 0; mt < 2; mt++)
#pragma unroll
        for (int f = 0; f < 8; f++)
#pragma unroll
            for (int q = 0; q < 4; q++) acc[mt][f][q] = 0.0f;

    issue(0); issue(1); issue(2);

#pragma unroll 1
    for (int k = 0; k < 16; k++) {
        CP_WAIT(2);
        __syncthreads();
        if (k + 3 < 16) issue(k + 3);
        else            CP_COMMIT();

        const uint32_t boff = (uint32_t)(k & (NSTAGE - 1)) * STAGEB;
#pragma unroll
        for (int ks = 0; ks < 2; ks++) {
            const uint32_t off = boff + ks * 32;
            uint32_t a[2][4], b[4][4];
#pragma unroll
            for (int mt = 0; mt < 2; mt++)
                ldm4(a[mt][0], a[mt][1], a[mt][2], a[mt][3], aBase[mt] + off);
#pragma unroll
            for (int g = 0; g < 4; g++)
                ldm4(b[g][0], b[g][1], b[g][2], b[g][3], bBase[g] + off);
#pragma unroll
            for (int mt = 0; mt < 2; mt++)
#pragma unroll
                for (int g = 0; g < 4; g++)
#pragma unroll
                    for (int j = 0; j < 2; j++)
                        mma16816(acc[mt][g * 2 + j],
                                 a[mt][0], a[mt][1], a[mt][2], a[mt][3],
                                 b[g][j], b[g][j + 2]);
        }
    }

    // --- epilogue ---
#pragma unroll
    for (int mt = 0; mt < 2; mt++) {
        const int r0 = m0 + w_m * 32 + mt * 16 + (lane >> 2);
#pragma unroll
        for (int g = 0; g < 4; g++)
#pragma unroll
            for (int j = 0; j < 2; j++) {
                const int cl = w_n * 64 + g * 16 + j * 8 + (lane & 3) * 2;
                const float* d = acc[mt][g * 2 + j];
                const float b0 = bias_s[cl], b1 = bias_s[cl + 1];
                if (CoutH) {
                    __half2 v0 = __floats2half2_rn(d[0] + b0, d[1] + b1);
                    __half2 v1 = __floats2half2_rn(d[2] + b0, d[3] + b1);
                    *(__half2*)(CoutH + (size_t)r0 * HIDDEN + ncol0 + cl)       = v0;
                    *(__half2*)(CoutH + (size_t)(r0 + 8) * HIDDEN + ncol0 + cl) = v1;
                } else {
                    float2 v0 = make_float2(d[0] + b0, d[1] + b1);
                    float2 v1 = make_float2(d[2] + b0, d[3] + b1);
                    *(float2*)(CoutF + (size_t)r0 * HIDDEN + ncol0 + cl)       = v0;
                    *(float2*)(CoutF + (size_t)(r0 + 8) * HIDDEN + ncol0 + cl) = v1;
                }
            }
    }
}

// ---------------- attention (token-indexed fp16 K/V, fp32 Q) ----------------
__global__ __launch_bounds__(256) void attn_kernel(const int* __restrict__ c,
                                                   float* __restrict__ out_ctx)
{
    const int b   = blockIdx.x;
    const int tid = threadIdx.x;

    __shared__ float Qs[HEADS][DHEAD];
    __shared__ float Sc[SEQ * HEADS][17];
    __shared__ float Vs[2][SEQ * DHEAD];
    __shared__ int   cs[SEQ];

    ((float4*)Qs)[tid] = ((const float4*)(g_Q + (size_t)b * HIDDEN))[tid];
    if (tid < SEQ) cs[tid] = c[b * SEQ + tid];
    __syncthreads();

    // ---- scores: thread = (s,g) computes all 16 h ----
    {
        const int s = tid >> 4, g = tid & 15;
        const uint2* krow =
            (const uint2*)(g_Kv + (size_t)cs[s] * HIDDEN + g * DHEAD);
        float acc[16];
#pragma unroll
        for (int h = 0; h < 16; h++) acc[h] = 0.0f;
#pragma unroll
        for (int d4 = 0; d4 < 16; d4++) {
            uint2 raw = krow[d4];
            float2 f0 = __half22float2(*(__half2*)&raw.x);
            float2 f1 = __half22float2(*(__half2*)&raw.y);
#pragma unroll
            for (int h = 0; h < 16; h++) {
                float4 qv = *(const float4*)&Qs[h][d4 * 4];
                acc[h] += f0.x * qv.x + f0.y * qv.y + f1.x * qv.z + f1.y * qv.w;
            }
        }
#pragma unroll
        for (int h = 0; h < 16; h++) Sc[s * 16 + h][g] = acc[h] * 0.125f;
    }
    __syncthreads();

    // ---- softmax over g ----
    {
        float v[16];
        float* row = Sc[tid];
        float mx = -1e30f;
#pragma unroll
        for (int g = 0; g < 16; g++) { v[g] = row[g]; mx = fmaxf(mx, v[g]); }
        float sum = 0.0f;
#pragma unroll
        for (int g = 0; g < 16; g++) { v[g] = __expf(v[g] - mx); sum += v[g]; }
        float inv = 1.0f / sum;
#pragma unroll
        for (int g = 0; g < 16; g++) row[g] = v[g] * inv;
    }
    __syncthreads();

    // ---- AV: thread = (h, d-quad) ----
    const int h  = tid >> 4;
    const int dq = tid & 15;
    float4 acc = make_float4(0.f, 0.f, 0.f, 0.f);
#pragma unroll 1
    for (int s = 0; s < SEQ; s++) {
        float* vbuf = Vs[s & 1];
        {
            uint2 raw = ((const uint2*)(g_Vv + (size_t)cs[s] * HIDDEN))[tid];
            float2 f0 = __half22float2(*(__half2*)&raw.x);
            float2 f1 = __half22float2(*(__half2*)&raw.y);
            ((float4*)vbuf)[tid] = make_float4(f0.x, f0.y, f1.x, f1.y);
        }
        __syncthreads();
        const float* arow = Sc[s * 16 + h];
#pragma unroll
        for (int g = 0; g < 16; g++) {
            float a = arow[g];
            float4 v = ((const float4*)vbuf)[g * 16 + dq];
            acc.x = fmaf(a, v.x, acc.x);
            acc.y = fmaf(a, v.y, acc.y);
            acc.z = fmaf(a, v.z, acc.z);
            acc.w = fmaf(a, v.w, acc.w);
        }
    }
    *(float4*)(out_ctx + (size_t)b * HIDDEN + h * DHEAD + dq * 4) = acc;
}

// ---------------------------------------------------------------------------
extern "C" void kernel_launch(void* const* d_in, const int* in_sizes, int n_in,
                              void* d_out, int out_size)
{
    const int*   t   = (const int*)d_in[0];
    const int*   c   = (const int*)d_in[1];
    const float* emb = (const float*)d_in[2];
    const float* WQ  = (const float*)d_in[3];
    const float* bQ  = (const float*)d_in[4];
    const float* WK  = (const float*)d_in[5];
    const float* bK  = (const float*)d_in[6];
    const float* WV  = (const float*)d_in[7];
    const float* bV  = (const float*)d_in[8];
    float* out = (float*)d_out;

    float* out_target = out;
    float* out_ctx    = out + (size_t)BATCH * HIDDEN;

    // fp32 -> fp16 converts
    {
        int n4e = (VOCAB * EMBED) / 4;
        conv_kernel<<<(n4e + 255) / 256, 256>>>(emb, 0, n4e);
        int n4w = (HIDDEN * EMBED) / 4;
        conv_kernel<<<(n4w + 255) / 256, 256>>>(WQ, 1, n4w);
        conv_kernel<<<(n4w + 255) / 256, 256>>>(WK, 2, n4w);
        conv_kernel<<<(n4w + 255) / 256, 256>>>(WV, 3, n4w);
    }

    // GEMMs: per-token K/V tables (dense) + target Q / target_vector (gathered)
    cudaFuncSetAttribute(gemm_mma_kernel,
                         cudaFuncAttributeMaxDynamicSharedMemorySize, SMEM_DYN);
    {
        dim3 grid(16, NV_TILES + NT_TILES);
        gemm_mma_kernel<<<grid, 256, SMEM_DYN>>>(t, bQ, bK, bV, out_target);
    }

    // attention (token-indexed K/V) -> context_vector
    attn_kernel<<<BATCH, 256>>>(c, out_ctx);
}

// round 10
// speedup vs baseline: 5.2740x; 1.1653x over previous
#include <cuda_runtime.h>
#include <cuda_fp16.h>
#include <cstdint>

#define BATCH  4096
#define SEQ    16
#define EMBED  512
#define HIDDEN 1024
#define HEADS  16
#define DHEAD  64
#define VOCAB  50257
#define VPAD   50304                    // 393 * 128
#define NV_TILES 393
#define NT_TILES 32

// ---------------- device scratch (no cudaMalloc allowed) ----------------
__device__ float  g_Q[(size_t)BATCH * HIDDEN];                   // 16 MB
__device__ __half g_Kv[(size_t)VPAD * HIDDEN];                   // per-token K
__device__ __half g_Vv[(size_t)VPAD * HIDDEN];                   // per-token V
__device__ __half g_emb_h[(size_t)VPAD * EMBED];                 // padded, pad rows = 0
__device__ __half g_W_h[3u * HIDDEN * EMBED];                    // WQ,WK,WV fp16
__device__ int    g_flags[VPAD];
__device__ int    g_list[VPAD];
__device__ int    g_cnt[1];

// ---------------- helpers ----------------
__device__ __forceinline__ uint32_t smem_u32(const void* p) {
    uint32_t a;
    asm("{ .reg .u64 t; cvta.to.shared.u64 t, %1; cvt.u32.u64 %0, t; }"
        : "=r"(a) : "l"(p));
    return a;
}
__device__ __forceinline__ void cpa16(uint32_t dst, const void* src) {
    asm volatile("cp.async.cg.shared.global [%0], [%1], 16;"
                 :: "r"(dst), "l"(src) : "memory");
}
#define CP_COMMIT() asm volatile("cp.async.commit_group;" ::: "memory")
#define CP_WAIT(n)  asm volatile("cp.async.wait_group %0;" :: "n"(n) : "memory")

__device__ __forceinline__ void ldm4(uint32_t& r0, uint32_t& r1,
                                     uint32_t& r2, uint32_t& r3, uint32_t a) {
    asm volatile("ldmatrix.sync.aligned.m8n8.x4.shared.b16 {%0,%1,%2,%3}, [%4];"
                 : "=r"(r0), "=r"(r1), "=r"(r2), "=r"(r3) : "r"(a));
}
__device__ __forceinline__ void mma16816(float* d,
                                         uint32_t a0, uint32_t a1, uint32_t a2, uint32_t a3,
                                         uint32_t b0, uint32_t b1) {
    asm volatile(
        "mma.sync.aligned.m16n8k16.row.col.f32.f16.f16.f32 "
        "{%0,%1,%2,%3}, {%4,%5,%6,%7}, {%8,%9}, {%0,%1,%2,%3};"
        : "+f"(d[0]), "+f"(d[1]), "+f"(d[2]), "+f"(d[3])
        : "r"(a0), "r"(a1), "r"(a2), "r"(a3), "r"(b0), "r"(b1));
}

// ---------------- compaction chain (marks c AND t tokens) ----------------
__global__ __launch_bounds__(256) void zero_kernel() {
    int i = blockIdx.x * blockDim.x + threadIdx.x;
    if (i < VPAD) g_flags[i] = 0;
    if (i == 0) g_cnt[0] = 0;
}
__global__ __launch_bounds__(256) void mark_kernel(const int* __restrict__ c,
                                                   const int* __restrict__ t) {
    int i = blockIdx.x * blockDim.x + threadIdx.x;
    if (i < BATCH * SEQ) g_flags[c[i]] = 1;
    if (i < BATCH)       g_flags[t[i]] = 1;   // target tokens need V rows too
}
__global__ __launch_bounds__(256) void compact_kernel() {
    int i = blockIdx.x * blockDim.x + threadIdx.x;
    if (i < VPAD && g_flags[i]) {
        int pos = atomicAdd(g_cnt, 1);
        g_list[pos] = i;
    }
}
__global__ __launch_bounds__(256) void padfill_kernel() {
    int i = blockIdx.x * blockDim.x + threadIdx.x;
    int cnt = g_cnt[0];
    if (i >= cnt && i < VPAD) g_list[i] = VPAD - 1;   // pad slot (emb row = 0)
}

// ---------------- fp32 -> fp16 convert ----------------
__global__ __launch_bounds__(256) void conv_kernel(const float* __restrict__ src,
                                                   int dst_sel, int n4) {
    int i = blockIdx.x * blockDim.x + threadIdx.x;
    if (i >= n4) return;
    __half* dst = (dst_sel == 0) ? g_emb_h
                                 : g_W_h + (size_t)(dst_sel - 1) * HIDDEN * EMBED;
    float4 v = ((const float4*)src)[i];
    ((__half2*)dst)[2 * i]     = __floats2half2_rn(v.x, v.y);
    ((__half2*)dst)[2 * i + 1] = __floats2half2_rn(v.z, v.w);
}

// ---------------- fp16 mma.sync GEMM (128x128 tile, occ 2) ------------------
// grid = (16, 425):
//   by <  393: compacted used-token rows -> K/V tables (nt<8 WK, nt>=8 WV),
//              CTAs past g_cnt exit early; outputs scattered by token id.
//   by >= 393: gathered t rows -> fp32 Q (nt<8 only; nt>=8 exits).
#define ROWB    80
#define TILEX   (128 * ROWB)            // 10240 B
#define STAGEB  (2 * TILEX)             // 20480 B
#define NSTAGE  4
#define SMEM_DYN (NSTAGE * STAGEB)      // 81920 B

__global__ __launch_bounds__(256, 2) void gemm_mma_kernel(
    const int* __restrict__ t,
    const float* __restrict__ bQ, const float* __restrict__ bK,
    const float* __restrict__ bV)
{
    extern __shared__ char smdyn[];
    __shared__ float bias_s[128];
    __shared__ int   rowid_s[128];

    const int tid  = threadIdx.x;
    const int lane = tid & 31;
    const int w    = tid >> 5;

    const int  nt    = blockIdx.x;             // 0..15
    const int  by    = blockIdx.y;             // 0..424
    const bool is_t  = (by >= NV_TILES);
    const int  m0    = (is_t ? by - NV_TILES : by) * 128;

    if (is_t && nt >= 8) return;               // target side: WQ only
    if (!is_t) {                                // vocab side: live tiles only
        const int cnt = g_cnt[0];
        if (m0 >= cnt) return;
    }

    const int  msel  = is_t ? 0 : ((nt < 8) ? 1 : 2);   // WQ / WK / WV
    const float* bias = is_t ? bQ : ((nt < 8) ? bK : bV);
    __half* CoutH = is_t ? nullptr : ((nt < 8) ? g_Kv : g_Vv);
    const int ncol0 = (nt & 7) * 128;

    const uint32_t smb = smem_u32(smdyn);

    if (tid < 128) {
        bias_s[tid]  = bias[ncol0 + tid];
        rowid_s[tid] = is_t ? (m0 + tid) : g_list[m0 + tid];
    }

    // --- cp.async: 128 rows x 4 segs(16B) per matrix; 256 thr -> 2 segs each ---
    const int rr = tid >> 1;                   // 0..127
    const int ss = (tid & 1) * 2;              // seg pair 0 or 2
    const int arow = is_t ? t[m0 + rr] : g_list[m0 + rr];
    const __half* pa = g_emb_h + (size_t)arow * EMBED + ss * 8;
    const __half* pb = g_W_h + (size_t)msel * HIDDEN * EMBED
                     + (size_t)(ncol0 + rr) * EMBED + ss * 8;
    const uint32_t dd = (uint32_t)(rr * ROWB + ss * 16);

    auto issue = [&](int k) {
        const uint32_t d0 = smb + (uint32_t)(k & (NSTAGE - 1)) * STAGEB + dd;
        const int ke = k * 32;
        cpa16(d0,              pa + ke);
        cpa16(d0 + 16,         pa + ke + 8);
        cpa16(d0 + TILEX,      pb + ke);
        cpa16(d0 + TILEX + 16, pb + ke + 8);
        CP_COMMIT();
    };

    // --- ldmatrix bases: 8 warps = 4 M x 2 N, warp tile 32x64 ---
    const int w_m = w & 3;
    const int w_n = w >> 2;
    const int lrow = lane & 15;
    const int lhalf = (lane >> 4) * 16;
    uint32_t aBase[2], bBase[4];
#pragma unroll
    for (int mt = 0; mt < 2; mt++)
        aBase[mt] = smb + (uint32_t)((w_m * 32 + mt * 16 + lrow) * ROWB + lhalf);
#pragma unroll
    for (int g = 0; g < 4; g++)
        bBase[g] = smb + TILEX + (uint32_t)((w_n * 64 + g * 16 + lrow) * ROWB + lhalf);

    float acc[2][8][4];
#pragma unroll
    for (int mt = 0; mt < 2; mt++)
#pragma unroll
        for (int f = 0; f < 8; f++)
#pragma unroll
            for (int q = 0; q < 4; q++) acc[mt][f][q] = 0.0f;

    issue(0); issue(1); issue(2);

#pragma unroll 1
    for (int k = 0; k < 16; k++) {
        CP_WAIT(2);
        __syncthreads();
        if (k + 3 < 16) issue(k + 3);
        else            CP_COMMIT();

        const uint32_t boff = (uint32_t)(k & (NSTAGE - 1)) * STAGEB;
#pragma unroll
        for (int ks = 0; ks < 2; ks++) {
            const uint32_t off = boff + ks * 32;
            uint32_t a[2][4], b[4][4];
#pragma unroll
            for (int mt = 0; mt < 2; mt++)
                ldm4(a[mt][0], a[mt][1], a[mt][2], a[mt][3], aBase[mt] + off);
#pragma unroll
            for (int g = 0; g < 4; g++)
                ldm4(b[g][0], b[g][1], b[g][2], b[g][3], bBase[g] + off);
#pragma unroll
            for (int mt = 0; mt < 2; mt++)
#pragma unroll
                for (int g = 0; g < 4; g++)
#pragma unroll
                    for (int j = 0; j < 2; j++)
                        mma16816(acc[mt][g * 2 + j],
                                 a[mt][0], a[mt][1], a[mt][2], a[mt][3],
                                 b[g][j], b[g][j + 2]);
        }
    }

    // --- epilogue: scatter vocab rows by token id; dense for Q ---
#pragma unroll
    for (int mt = 0; mt < 2; mt++) {
        const int rl = w_m * 32 + mt * 16 + (lane >> 2);   // tile-local rows rl, rl+8
        const int row0 = rowid_s[rl];
        const int row1 = rowid_s[rl + 8];
#pragma unroll
        for (int g = 0; g < 4; g++)
#pragma unroll
            for (int j = 0; j < 2; j++) {
                const int cl = w_n * 64 + g * 16 + j * 8 + (lane & 3) * 2;
                const float* d = acc[mt][g * 2 + j];
                const float b0 = bias_s[cl], b1 = bias_s[cl + 1];
                if (CoutH) {
                    __half2 v0 = __floats2half2_rn(d[0] + b0, d[1] + b1);
                    __half2 v1 = __floats2half2_rn(d[2] + b0, d[3] + b1);
                    *(__half2*)(CoutH + (size_t)row0 * HIDDEN + ncol0 + cl) = v0;
                    *(__half2*)(CoutH + (size_t)row1 * HIDDEN + ncol0 + cl) = v1;
                } else {
                    float2 v0 = make_float2(d[0] + b0, d[1] + b1);
                    float2 v1 = make_float2(d[2] + b0, d[3] + b1);
                    *(float2*)(g_Q + (size_t)row0 * HIDDEN + ncol0 + cl) = v0;
                    *(float2*)(g_Q + (size_t)row1 * HIDDEN + ncol0 + cl) = v1;
                }
            }
    }
}

// -------- attention (token-indexed fp16 K/V) + target_vector gather --------
__global__ __launch_bounds__(256) void attn_kernel(const int* __restrict__ t,
                                                   const int* __restrict__ c,
                                                   float* __restrict__ out_target,
                                                   float* __restrict__ out_ctx)
{
    const int b   = blockIdx.x;
    const int tid = threadIdx.x;

    __shared__ float Qs[HEADS][DHEAD];
    __shared__ float Sc[SEQ * HEADS][17];
    __shared__ float Vs[2][SEQ * DHEAD];
    __shared__ int   cs[SEQ];

    ((float4*)Qs)[tid] = ((const float4*)(g_Q + (size_t)b * HIDDEN))[tid];
    if (tid < SEQ) cs[tid] = c[b * SEQ + tid];

    // target_vector[b] = V-table row of token t[b] (fp16 -> fp32)
    {
        const int tb = t[b];
        uint2 raw = ((const uint2*)(g_Vv + (size_t)tb * HIDDEN))[tid];
        float2 f0 = __half22float2(*(__half2*)&raw.x);
        float2 f1 = __half22float2(*(__half2*)&raw.y);
        *(float4*)(out_target + (size_t)b * HIDDEN + tid * 4) =
            make_float4(f0.x, f0.y, f1.x, f1.y);
    }
    __syncthreads();

    // ---- scores: thread = (s,g) computes all 16 h ----
    {
        const int s = tid >> 4, g = tid & 15;
        const uint2* krow =
            (const uint2*)(g_Kv + (size_t)cs[s] * HIDDEN + g * DHEAD);
        float acc[16];
#pragma unroll
        for (int h = 0; h < 16; h++) acc[h] = 0.0f;
#pragma unroll
        for (int d4 = 0; d4 < 16; d4++) {
            uint2 raw = krow[d4];
            float2 f0 = __half22float2(*(__half2*)&raw.x);
            float2 f1 = __half22float2(*(__half2*)&raw.y);
#pragma unroll
            for (int h = 0; h < 16; h++) {
                float4 qv = *(const float4*)&Qs[h][d4 * 4];
                acc[h] += f0.x * qv.x + f0.y * qv.y + f1.x * qv.z + f1.y * qv.w;
            }
        }
#pragma unroll
        for (int h = 0; h < 16; h++) Sc[s * 16 + h][g] = acc[h] * 0.125f;
    }
    __syncthreads();

    // ---- softmax over g ----
    {
        float v[16];
        float* row = Sc[tid];
        float mx = -1e30f;
#pragma unroll
        for (int g = 0; g < 16; g++) { v[g] = row[g]; mx = fmaxf(mx, v[g]); }
        float sum = 0.0f;
#pragma unroll
        for (int g = 0; g < 16; g++) { v[g] = __expf(v[g] - mx); sum += v[g]; }
        float inv = 1.0f / sum;
#pragma unroll
        for (int g = 0; g < 16; g++) row[g] = v[g] * inv;
    }
    __syncthreads();

    // ---- AV: thread = (h, d-quad) ----
    const int h  = tid >> 4;
    const int dq = tid & 15;
    float4 acc = make_float4(0.f, 0.f, 0.f, 0.f);
#pragma unroll 1
    for (int s = 0; s < SEQ; s++) {
        float* vbuf = Vs[s & 1];
        {
            uint2 raw = ((const uint2*)(g_Vv + (size_t)cs[s] * HIDDEN))[tid];
            float2 f0 = __half22float2(*(__half2*)&raw.x);
            float2 f1 = __half22float2(*(__half2*)&raw.y);
            ((float4*)vbuf)[tid] = make_float4(f0.x, f0.y, f1.x, f1.y);
        }
        __syncthreads();
        const float* arow = Sc[s * 16 + h];
#pragma unroll
        for (int g = 0; g < 16; g++) {
            float a = arow[g];
            float4 v = ((const float4*)vbuf)[g * 16 + dq];
            acc.x = fmaf(a, v.x, acc.x);
            acc.y = fmaf(a, v.y, acc.y);
            acc.z = fmaf(a, v.z, acc.z);
            acc.w = fmaf(a, v.w, acc.w);
        }
    }
    *(float4*)(out_ctx + (size_t)b * HIDDEN + h * DHEAD + dq * 4) = acc;
}

// ---------------------------------------------------------------------------
extern "C" void kernel_launch(void* const* d_in, const int* in_sizes, int n_in,
                              void* d_out, int out_size)
{
    const int*   t   = (const int*)d_in[0];
    const int*   c   = (const int*)d_in[1];
    const float* emb = (const float*)d_in[2];
    const float* WQ  = (const float*)d_in[3];
    const float* bQ  = (const float*)d_in[4];
    const float* WK  = (const float*)d_in[5];
    const float* bK  = (const float*)d_in[6];
    const float* WV  = (const float*)d_in[7];
    const float* bV  = (const float*)d_in[8];
    float* out = (float*)d_out;

    float* out_target = out;
    float* out_ctx    = out + (size_t)BATCH * HIDDEN;

    // used-token compaction chain (c AND t)
    {
        int gz = (VPAD + 255) / 256;
        zero_kernel<<<gz, 256>>>();
        mark_kernel<<<(BATCH * SEQ + 255) / 256, 256>>>(c, t);
        compact_kernel<<<gz, 256>>>();
        padfill_kernel<<<gz, 256>>>();
    }

    // fp32 -> fp16 converts
    {
        int n4e = (VOCAB * EMBED) / 4;
        conv_kernel<<<(n4e + 255) / 256, 256>>>(emb, 0, n4e);
        int n4w = (HIDDEN * EMBED) / 4;
        conv_kernel<<<(n4w + 255) / 256, 256>>>(WQ, 1, n4w);
        conv_kernel<<<(n4w + 255) / 256, 256>>>(WK, 2, n4w);
        conv_kernel<<<(n4w + 255) / 256, 256>>>(WV, 3, n4w);
    }

    // GEMMs: K/V for used tokens (scattered) + Q for targets
    cudaFuncSetAttribute(gemm_mma_kernel,
                         cudaFuncAttributeMaxDynamicSharedMemorySize, SMEM_DYN);
    {
        dim3 grid(16, NV_TILES + NT_TILES);
        gemm_mma_kernel<<<grid, 256, SMEM_DYN>>>(t, bQ, bK, bV);
    }

    // attention + target_vector gather
    attn_kernel<<<BATCH, 256>>>(t, c, out_target, out_ctx);
}